// round 14
// baseline (speedup 1.0000x reference)
#include <cuda_runtime.h>

#define BV 2
#define CV 3
#define HV 512
#define WV 512
#define NPIX (HV*WV)
#define CN (CV*NPIX)
#define BCN (BV*CN)
#define GH 64
#define GW 64
#define NBIN 9
#define NGRID (BV*CV*GH*GW*NBIN*2)
#define EPSF 1e-8f
#define CG_TOL 1e-4f

// ---------------- scratch (device globals; no allocation) ----------------
__device__ float g_x[BCN], g_x2[BCN];
__device__ float g_r[BCN];
__device__ float g_p[BCN], g_p2[BCN];
__device__ float g_t[BCN], g_t2[BCN];
__device__ float g_tp[BCN];
__device__ float g_v[BV*5*CN];        // reused: [0..BCN) holds c-term for stage 1
__device__ float g_tgt[BV*5*CN];
__device__ float g_gridA[NGRID], g_gridB[NGRID];
__device__ float g_partN[BV*384];
__device__ float g_partDf[BV*384];
__device__ float g_partR[BV*768];
__device__ float g_r0[BV];
__device__ float g_rnS[2][BV];
__device__ int   g_doneS[2][BV];

// sparse tap metadata, zero-padded (exact: fmaf(0,x,a)==a for finite x)
__device__ int   g_dknt[2][6];
__device__ int   g_dkdy[2][6][25];
__device__ int   g_dkdx[2][6][25];
__device__ float g_dkv [2][6][25];
__device__ float g_dkw2[2][6];
__device__ int   g_rknt[2][5];
__device__ int   g_rkdy[2][5][25];
__device__ int   g_rkdx[2][5][25];
__device__ float g_rkv [2][5][25];
__device__ int   g_fastDk[2];
__device__ float g_scale1[2];
__device__ int   g_allp2[2];
__device__ int   g_fusedDen[2];
__device__ int   g_Snt4[2];
__device__ float g_Sv[2][84];
__device__ int   g_So40[2][84];

__device__ __forceinline__ float powx(float a, float e){
    if (e == 0.0f) return 1.0f;
    if (e == 1.0f) return a;
    return powf(a, e);
}
__device__ __forceinline__ float sgnf(float v){
    return (v > 0.f) ? 1.f : ((v < 0.f) ? -1.f : 0.f);
}

struct T4 { float v0,v1,v2,v3; int o0,o1,o2,o3; };
__device__ __forceinline__ T4 t4_fwd_rk(int s,int m,int st){
    T4 t;
    t.v0=g_rkv[s][m][0]; t.v1=g_rkv[s][m][1]; t.v2=g_rkv[s][m][2]; t.v3=g_rkv[s][m][3];
    t.o0=g_rkdy[s][m][0]*st+g_rkdx[s][m][0]; t.o1=g_rkdy[s][m][1]*st+g_rkdx[s][m][1];
    t.o2=g_rkdy[s][m][2]*st+g_rkdx[s][m][2]; t.o3=g_rkdy[s][m][3]*st+g_rkdx[s][m][3];
    return t;
}
__device__ __forceinline__ T4 t4_adj_rk(int s,int m,int st){
    T4 t;
    t.v0=g_rkv[s][m][0]; t.v1=g_rkv[s][m][1]; t.v2=g_rkv[s][m][2]; t.v3=g_rkv[s][m][3];
    t.o0=(4-g_rkdy[s][m][0])*st+(4-g_rkdx[s][m][0]); t.o1=(4-g_rkdy[s][m][1])*st+(4-g_rkdx[s][m][1]);
    t.o2=(4-g_rkdy[s][m][2])*st+(4-g_rkdx[s][m][2]); t.o3=(4-g_rkdy[s][m][3])*st+(4-g_rkdx[s][m][3]);
    return t;
}
__device__ __forceinline__ T4 t4_fwd_dk(int s,int n,int st){
    T4 t;
    t.v0=g_dkv[s][n][0]; t.v1=g_dkv[s][n][1]; t.v2=g_dkv[s][n][2]; t.v3=g_dkv[s][n][3];
    t.o0=g_dkdy[s][n][0]*st+g_dkdx[s][n][0]; t.o1=g_dkdy[s][n][1]*st+g_dkdx[s][n][1];
    t.o2=g_dkdy[s][n][2]*st+g_dkdx[s][n][2]; t.o3=g_dkdy[s][n][3]*st+g_dkdx[s][n][3];
    return t;
}
__device__ __forceinline__ T4 t4_adj_dk(int s,int n,int st){
    T4 t;
    t.v0=g_dkv[s][n][0]; t.v1=g_dkv[s][n][1]; t.v2=g_dkv[s][n][2]; t.v3=g_dkv[s][n][3];
    t.o0=(4-g_dkdy[s][n][0])*st+(4-g_dkdx[s][n][0]); t.o1=(4-g_dkdy[s][n][1])*st+(4-g_dkdx[s][n][1]);
    t.o2=(4-g_dkdy[s][n][2])*st+(4-g_dkdx[s][n][2]); t.o3=(4-g_dkdy[s][n][3])*st+(4-g_dkdx[s][n][3]);
    return t;
}
__device__ __forceinline__ float c4(const float* p, const T4& t, float a){
    a = fmaf(t.v0, p[t.o0], a);
    a = fmaf(t.v1, p[t.o1], a);
    a = fmaf(t.v2, p[t.o2], a);
    a = fmaf(t.v3, p[t.o3], a);
    return a;
}
__device__ __forceinline__ float cg_fwd_dk(const float* p,int s,int n,int nt,int st,float a){
    for (int t = 0; t < nt; t++) a = fmaf(g_dkv[s][n][t], p[g_dkdy[s][n][t]*st+g_dkdx[s][n][t]], a);
    return a;
}
__device__ __forceinline__ float cg_adj_dk(const float* p,int s,int n,int nt,int st,float a){
    for (int t = 0; t < nt; t++) a = fmaf(g_dkv[s][n][t], p[(4-g_dkdy[s][n][t])*st+(4-g_dkdx[s][n][t])], a);
    return a;
}
__device__ __forceinline__ float cg_fwd_rk(const float* p,int s,int m,int nt,int st,float a){
    for (int t = 0; t < nt; t++) a = fmaf(g_rkv[s][m][t], p[g_rkdy[s][m][t]*st+g_rkdx[s][m][t]], a);
    return a;
}
__device__ __forceinline__ float cg_adj_rk(const float* p,int s,int m,int nt,int st,float a){
    for (int t = 0; t < nt; t++) a = fmaf(g_rkv[s][m][t], p[(4-g_rkdy[s][m][t])*st+(4-g_rkdx[s][m][t])], a);
    return a;
}
__device__ __forceinline__ float alpha_reduce(int b, int slot, int tid,
                                              float* sh, float* sh2, float* s_alpha)
{
    float sn = 0.f, sd = 0.f;
    if (tid < 128){
        sn = g_partN [b*384+tid] + g_partN [b*384+128+tid] + g_partN [b*384+256+tid];
        sd = g_partDf[b*384+tid] + g_partDf[b*384+128+tid] + g_partDf[b*384+256+tid];
    }
    sh[tid] = sn; sh2[tid] = sd; __syncthreads();
    for (int o = 128; o; o >>= 1){
        if (tid < o){ sh[tid] += sh[tid+o]; sh2[tid] += sh2[tid+o]; }
        __syncthreads();
    }
    if (tid == 0){
        int dn = g_doneS[slot][b];
        *s_alpha = dn ? 0.f : sh[0]/(sh2[0] + 1e-12f);
    }
    __syncthreads();
    return *s_alpha;
}

// ---------------- prep ----------------
__global__ void k_prep(const float* __restrict__ dks, const float* __restrict__ dkw,
                       const float* __restrict__ rks, const float* __restrict__ rkw,
                       const float* __restrict__ rpow)
{
    if (threadIdx.x != 0 || blockIdx.x != 0) return;
    for (int s = 0; s < 2; s++){
        int fast = 1, center1 = 1; float sc1 = 0.f;
        for (int n = 0; n < 6; n++){
            float w2 = 2.f*dkw[s*6+n];
            g_dkw2[s][n] = w2;
            int cnt = 0;
            for (int j = 0; j < 25; j++){
                float v = dks[(s*6+n)*25 + j];
                if (v != 0.f){
                    g_dkdy[s][n][cnt] = j/5; g_dkdx[s][n][cnt] = j%5;
                    g_dkv [s][n][cnt] = v; cnt++;
                }
            }
            g_dknt[s][n] = cnt;
            for (int j = cnt; j < 25; j++){ g_dkdy[s][n][j]=0; g_dkdx[s][n][j]=0; g_dkv[s][n][j]=0.f; }
            if (w2 != 0.f){
                if (cnt == 1){
                    sc1 += w2*g_dkv[s][n][0]*g_dkv[s][n][0];
                    if (g_dkdy[s][n][0] != 2 || g_dkdx[s][n][0] != 2) center1 = 0;
                } else { fast = 0; center1 = 0; }
            }
        }
        g_fastDk[s] = fast;
        g_scale1[s] = sc1;
        int p2 = 1;
        for (int m = 0; m < 5; m++){
            if (rpow[s*5+m] != 2.0f) p2 = 0;
            int cnt = 0;
            for (int j = 0; j < 25; j++){
                float v = rks[(s*5+m)*25 + j];
                if (v != 0.f){
                    g_rkdy[s][m][cnt] = j/5; g_rkdx[s][m][cnt] = j%5;
                    g_rkv [s][m][cnt] = v; cnt++;
                }
            }
            g_rknt[s][m] = cnt;
            for (int j = cnt; j < 25; j++){ g_rkdy[s][m][j]=0; g_rkdx[s][m][j]=0; g_rkv[s][m][j]=0.f; }
        }
        g_allp2[s] = p2;
        g_fusedDen[s] = p2 && center1;

        float Sbuf[81];
        for (int j = 0; j < 81; j++) Sbuf[j] = 0.f;
        for (int m = 0; m < 5; m++){
            float wp = rkw[s*5+m]*rpow[s*5+m];
            int nt = g_rknt[s][m];
            for (int t1 = 0; t1 < nt; t1++)
                for (int t2 = 0; t2 < nt; t2++){
                    int ody = g_rkdy[s][m][t1] - g_rkdy[s][m][t2];
                    int odx = g_rkdx[s][m][t1] - g_rkdx[s][m][t2];
                    Sbuf[(ody+4)*9 + (odx+4)] += wp*g_rkv[s][m][t1]*g_rkv[s][m][t2];
                }
        }
        int cnt = 0;
        for (int j = 0; j < 81; j++){
            if (Sbuf[j] != 0.f){
                g_Sv[s][cnt] = Sbuf[j];
                g_So40[s][cnt] = (j/9 - 4)*40 + (j%9 - 4);
                cnt++;
            }
        }
        while (cnt & 3){ g_Sv[s][cnt] = 0.f; g_So40[s][cnt] = 0; cnt++; }
        g_Snt4[s] = cnt;
    }
}

// ---------------- plain 15x15 conv - sub (CG init only), 32x64 tile ----------------
__global__ void __launch_bounds__(256)
k_conv15(const float* __restrict__ src, float* __restrict__ dst,
         const float* __restrict__ kern, const float* __restrict__ sub)
{
    int z = blockIdx.z; int b = z / CV;
    __shared__ float tile[78][46];
    __shared__ float sk[225];
    const float* sp = src + z*NPIX;
    int X0 = blockIdx.x*32, Y0 = blockIdx.y*64;
    int x0 = X0 - 7, y0 = Y0 - 7;
    int tx_ = threadIdx.x, ty_ = threadIdx.y;
    int tid = ty_*32 + tx_;
    bool inter = (Y0 >= 7) && (Y0 + 71 <= HV) && (X0 >= 7) && (X0 + 39 <= WV);
    if (inter){
        for (int row = ty_; row < 78; row += 8){
            const float* rp = sp + (y0+row)*WV + x0;
            for (int col = tx_; col < 46; col += 32) tile[row][col] = rp[col];
        }
    } else {
        for (int row = ty_; row < 78; row += 8){
            int gy = y0 + row;
            bool iny = (unsigned)gy < HV;
            for (int col = tx_; col < 46; col += 32){
                int gx = x0 + col;
                tile[row][col] = (iny && (unsigned)gx < WV) ? sp[gy*WV+gx] : 0.f;
            }
        }
    }
    const float* kb = kern + b*225;
    for (int i = tid; i < 225; i += 256) sk[i] = kb[i];
    __syncthreads();
    float acc[8] = {0,0,0,0,0,0,0,0};
    int rbase = ty_*8;
    for (int v = 0; v < 15; v++){
        float win[22];
        #pragma unroll
        for (int j = 0; j < 22; j++) win[j] = tile[rbase+j][tx_+v];
        #pragma unroll
        for (int u = 0; u < 15; u++){
            float kv = sk[u*15+v];
            #pragma unroll
            for (int q = 0; q < 8; q++) acc[q] = fmaf(kv, win[u+q], acc[q]);
        }
    }
    int gx = X0 + tx_;
    int gyb = Y0 + rbase;
    #pragma unroll
    for (int q = 0; q < 8; q++){
        int oi = z*NPIX + (gyb+q)*WV + gx;
        float o = acc[q];
        if (sub) o -= sub[oi];
        dst[oi] = o;
    }
}

// ---- fused: beta/done + p update + Kp conv + num partial + den partial --------------
__global__ void __launch_bounds__(256,6)
k_pstep(const float* __restrict__ pold, float* __restrict__ pnew,
        float* __restrict__ kp, const float* __restrict__ rsrc,
        const float* __restrict__ kern,
        const float* __restrict__ rkw, const float* __restrict__ rpow,
        int stage, int first, int slot)
{
    int z = blockIdx.z; int b = z/CV, c = z - b*CV;
    int tx_ = threadIdx.x, ty_ = threadIdx.y;
    int tid = ty_*32 + tx_;
    __shared__ float pn[78][46];
    __shared__ float sk[225];
    __shared__ float sh[256];
    __shared__ float sh2[256];
    __shared__ float s_beta;
    __shared__ int s_freeze;

    float a = g_partR[b*768+tid] + g_partR[b*768+256+tid] + g_partR[b*768+512+tid];
    sh[tid] = a; __syncthreads();
    for (int o = 128; o; o >>= 1){ if (tid < o) sh[tid] += sh[tid+o]; __syncthreads(); }
    if (tid == 0){
        float nrn = sh[0];
        int done_prev = first ? 0 : g_doneS[slot][b];
        float rn_prev = first ? 1.f : g_rnS[slot][b];
        float r0 = first ? nrn : g_r0[b];
        int conv_now = (!first) && (nrn < CG_TOL*r0);
        s_beta = first ? 0.f : nrn/(rn_prev + 1e-20f);
        s_freeze = first ? 0 : (done_prev | conv_now);
        if (blockIdx.x == 0 && blockIdx.y == 0 && c == 0){
            g_doneS[slot^1][b] = done_prev | conv_now;
            g_rnS[slot^1][b] = done_prev ? rn_prev : nrn;
            if (first) g_r0[b] = nrn;
        }
    }
    __syncthreads();
    int X0 = blockIdx.x*32, Y0 = blockIdx.y*64;
    if (s_freeze){
        const float* pop = pold + z*NPIX;
        float* pno = pnew + z*NPIX;
        for (int row = ty_; row < 64; row += 8){
            int gi = (Y0+row)*WV + X0 + tx_;
            pno[gi] = pop[gi];
        }
        return;
    }
    float beta = s_beta;
    const float* rp = rsrc + z*NPIX;
    const float* pop = pold + z*NPIX;
    float* pno = pnew + z*NPIX;
    int x0 = X0 - 7, y0 = Y0 - 7;
    bool inter = (Y0 >= 7) && (Y0 + 71 <= HV) && (X0 >= 7) && (X0 + 39 <= WV);
    float s = 0.f;
    if (inter){
        for (int row = ty_; row < 78; row += 8){
            const float* rr = rp + (y0+row)*WV + x0;
            const float* pr2 = pop + (y0+row)*WV + x0;
            float* pw = pno + (y0+row)*WV + x0;
            bool rin = (row >= 7 && row < 71);
            for (int col = tx_; col < 46; col += 32){
                float rv = rr[col];
                float v = first ? rv : fmaf(beta, pr2[col], rv);
                if (rin && col >= 7 && col < 39){
                    pw[col] = v;
                    s = fmaf(rv, v, s);
                }
                pn[row][col] = v;
            }
        }
    } else {
        for (int row = ty_; row < 78; row += 8){
            int gy = y0 + row;
            bool iny = (unsigned)gy < HV;
            bool rin = (row >= 7 && row < 71);
            for (int col = tx_; col < 46; col += 32){
                int gx = x0 + col;
                float v = 0.f;
                if (iny && (unsigned)gx < WV){
                    int gi = gy*WV + gx;
                    float rv = rp[gi];
                    v = first ? rv : fmaf(beta, pop[gi], rv);
                    if (rin && col >= 7 && col < 39){
                        pno[gi] = v;
                        s = fmaf(rv, v, s);
                    }
                }
                pn[row][col] = v;
            }
        }
    }
    const float* kb = kern + b*225;
    for (int i = tid; i < 225; i += 256) sk[i] = kb[i];
    __syncthreads();
    float acc[8] = {0,0,0,0,0,0,0,0};
    int rbase = ty_*8;
    for (int v = 0; v < 15; v++){
        float win[22];
        #pragma unroll
        for (int j = 0; j < 22; j++) win[j] = pn[rbase+j][tx_+v];
        #pragma unroll
        for (int u = 0; u < 15; u++){
            float kv = sk[u*15+v];
            #pragma unroll
            for (int q = 0; q < 8; q++) acc[q] = fmaf(kv, win[u+q], acc[q]);
        }
    }
    float* ko = kp + z*NPIX;
    #pragma unroll
    for (int q = 0; q < 8; q++)
        ko[(Y0+rbase+q)*WV + X0 + tx_] = acc[q];

    float sden = 0.f;
    {
        float sc1 = g_scale1[stage];
        #pragma unroll
        for (int q = 0; q < 8; q++) sden = fmaf(sc1*acc[q], acc[q], sden);
        for (int m = 0; m < 5; m++){
            int nt = g_rknt[stage][m];
            float pmv = rpow[stage*5+m];
            float wc = rkw[stage*5+m]*pmv*(pmv-1.f);
            if (nt <= 4){
                T4 tf = t4_fwd_rk(stage, m, 46);
                #pragma unroll
                for (int q = 0; q < 8; q++){
                    float rv = c4(&pn[rbase+q+5][tx_+5], tf, 0.f);
                    sden = fmaf(wc*rv, rv, sden);
                }
            } else {
                for (int q = 0; q < 8; q++){
                    float rv = cg_fwd_rk(&pn[rbase+q+5][tx_+5], stage, m, nt, 46, 0.f);
                    sden = fmaf(wc*rv, rv, sden);
                }
            }
        }
    }
    __syncthreads();
    sh[tid] = s; sh2[tid] = sden; __syncthreads();
    for (int o = 128; o; o >>= 1){
        if (tid < o){ sh[tid] += sh[tid+o]; sh2[tid] += sh2[tid+o]; }
        __syncthreads();
    }
    if (tid == 0){
        g_partN [b*384 + c*128 + blockIdx.y*16 + blockIdx.x] = sh[0];
        g_partDf[b*384 + c*128 + blockIdx.y*16 + blockIdx.x] = sh2[0];
    }
}

// ---------------- final-iteration axpy (stage 1 only) ----------------
__global__ void k_axpy_final(const float* __restrict__ xsrc, const float* __restrict__ psrc,
                             float* __restrict__ xdst, int slot)
{
    int b = blockIdx.y;
    int tid = threadIdx.x;
    __shared__ float sh[256], sh2[256], s_alpha;
    float al = alpha_reduce(b, slot, tid, sh, sh2, &s_alpha);
    const float* xp = xsrc + b*CN;
    const float* pp = psrc + b*CN;
    float* xo = xdst + b*CN;
    for (int i = blockIdx.x*256 + tid; i < CN; i += 65536)
        xo[i] = fmaf(al, pp[i], xp[i]);
}

// ---------------- fused gradient + x/t update + r-norm partial ----------------
__global__ void __launch_bounds__(256,6)
k_gradfull(const float* __restrict__ xsrc, const float* __restrict__ psrc,
           const float* __restrict__ tsrc, const float* __restrict__ tpsrc,
           float* __restrict__ xdst, float* __restrict__ tdst,
           const float* __restrict__ tgt, const float* __restrict__ csrc,
           float* __restrict__ rdst, float* __restrict__ vdst,
           const float* __restrict__ kern,
           const float* __restrict__ rkw, const float* __restrict__ rpow,
           int stage, int slot, int first)
{
    int z = blockIdx.z; int b = z/CV, c = z - b*CV;
    int tx_ = threadIdx.x, ty_ = threadIdx.y;
    int tid = ty_*32 + tx_;
    int X0 = blockIdx.x*32, Y0 = blockIdx.y*32;

    int dn = first ? 0 : g_doneS[slot][b];
    if (dn){
        const float* xp = xsrc + z*NPIX;
        const float* tp = tsrc + z*NPIX;
        float* xo = xdst + z*NPIX;
        float* to = tdst + z*NPIX;
        for (int row = ty_; row < 32; row += 8){
            int gi = (Y0+row)*WV + X0 + tx_;
            xo[gi] = xp[gi];
            to[gi] = tp[gi];
        }
        return;
    }

    __shared__ float st[54][54];
    __shared__ float sx[40][40];
    __shared__ float pool[6480];
    __shared__ float sk[225];
    __shared__ float sSv[84];
    __shared__ int   sSo[84];
    __shared__ float sh[256];
    __shared__ float sh2[256];
    __shared__ float s_alpha;

    if (first){
        if (tid == 0) s_alpha = 0.f;
        __syncthreads();
    } else {
        alpha_reduce(b, slot, tid, sh, sh2, &s_alpha);
    }
    float al = s_alpha;

    const float* xp = xsrc + z*NPIX;
    const float* pp = psrc + z*NPIX;
    const float* tp = tsrc + z*NPIX;
    const float* tq = tpsrc + z*NPIX;
    float* xo = xdst + z*NPIX;
    float* to = tdst + z*NPIX;

    bool inter = (Y0 >= 11) && (Y0 + 43 <= HV) && (X0 >= 11) && (X0 + 43 <= WV);
    bool fastD = inter && (g_fastDk[stage] != 0);
    int p2 = g_allp2[stage];
    float* su = pool;
    float* sbuf = pool + 2116;

    if (fastD){
        for (int row = ty_; row < 46; row += 8){
            const float* a1 = tp + (Y0-7+row)*WV + X0-7;
            const float* a2 = tq + (Y0-7+row)*WV + X0-7;
            float* a3 = to + (Y0-7+row)*WV + X0-7;
            bool rin = (row >= 7 && row < 39);
            for (int col = tx_; col < 46; col += 32){
                float v = first ? a1[col] : fmaf(al, a2[col], a1[col]);
                if (rin && col >= 7 && col < 39) a3[col] = v;
                st[row][col] = v;
            }
        }
        for (int row = ty_; row < 40; row += 8){
            const float* a1 = xp + (Y0-4+row)*WV + X0-4;
            const float* a2 = pp + (Y0-4+row)*WV + X0-4;
            float* a3 = xo + (Y0-4+row)*WV + X0-4;
            bool rin = (row >= 4 && row < 36);
            for (int col = tx_; col < 40; col += 32){
                float v = first ? a1[col] : fmaf(al, a2[col], a1[col]);
                if (rin && col >= 4 && col < 36) a3[col] = v;
                sx[row][col] = v;
            }
        }
    } else if (inter){
        for (int row = ty_; row < 54; row += 8){
            const float* a1 = tp + (Y0-11+row)*WV + X0-11;
            const float* a2 = tq + (Y0-11+row)*WV + X0-11;
            float* a3 = to + (Y0-11+row)*WV + X0-11;
            bool rin = (row >= 11 && row < 43);
            for (int col = tx_; col < 54; col += 32){
                float v = first ? a1[col] : fmaf(al, a2[col], a1[col]);
                if (rin && col >= 11 && col < 43) a3[col] = v;
                st[row][col] = v;
            }
        }
        for (int row = ty_; row < 40; row += 8){
            const float* a1 = xp + (Y0-4+row)*WV + X0-4;
            const float* a2 = pp + (Y0-4+row)*WV + X0-4;
            float* a3 = xo + (Y0-4+row)*WV + X0-4;
            bool rin = (row >= 4 && row < 36);
            for (int col = tx_; col < 40; col += 32){
                float v = first ? a1[col] : fmaf(al, a2[col], a1[col]);
                if (rin && col >= 4 && col < 36) a3[col] = v;
                sx[row][col] = v;
            }
        }
    } else {
        for (int row = ty_; row < 54; row += 8){
            int gy = Y0 - 11 + row;
            bool iny = (unsigned)gy < HV;
            bool rin = (row >= 11 && row < 43);
            for (int col = tx_; col < 54; col += 32){
                int gx = X0 - 11 + col;
                float v = 0.f;
                if (iny && (unsigned)gx < WV){
                    int gi = gy*WV + gx;
                    v = first ? tp[gi] : fmaf(al, tq[gi], tp[gi]);
                    if (rin && col >= 11 && col < 43) to[gi] = v;
                }
                st[row][col] = v;
            }
        }
        for (int row = ty_; row < 40; row += 8){
            int gy = Y0 - 4 + row;
            bool iny = (unsigned)gy < HV;
            bool rin = (row >= 4 && row < 36);
            for (int col = tx_; col < 40; col += 32){
                int gx = X0 - 4 + col;
                float v = 0.f;
                if (iny && (unsigned)gx < WV){
                    int gi = gy*WV + gx;
                    v = first ? xp[gi] : fmaf(al, pp[gi], xp[gi]);
                    if (rin && col >= 4 && col < 36) xo[gi] = v;
                }
                sx[row][col] = v;
            }
        }
    }
    const float* kb = kern + b*225;
    for (int i = tid; i < 225; i += 256) sk[i] = kb[224 - i];
    for (int i = tid; i < 84; i += 256){ sSv[i] = g_Sv[stage][i]; sSo[i] = g_So40[stage][i]; }
    if (!fastD)
        for (int i = tid; i < 2116; i += 256) su[i] = 0.f;
    __syncthreads();

    if (!fastD){
        for (int n = 0; n < 6; n++){
            float w2 = g_dkw2[stage][n];
            if (w2 == 0.f) continue;
            int nt = g_dknt[stage][n];
            if (nt == 1){
                int dy = g_dkdy[stage][n][0], dx = g_dkdx[stage][n][0];
                float vv0 = g_dkv[stage][n][0];
                float wv2 = w2*vv0*vv0;
                if (inter){
                    for (int row = ty_; row < 46; row += 8)
                        for (int col = tx_; col < 46; col += 32)
                            su[row*46+col] = fmaf(wv2, st[row+4][col+4], su[row*46+col]);
                } else {
                    for (int row = ty_; row < 46; row += 8){
                        int gy = Y0 - 7 + row;
                        int iy = gy + 2 - dy;
                        bool okr = ((unsigned)gy < HV) && ((unsigned)iy < HV);
                        for (int col = tx_; col < 46; col += 32){
                            int gx = X0 - 7 + col;
                            int ix = gx + 2 - dx;
                            if (okr && (unsigned)gx < WV && (unsigned)ix < WV)
                                su[row*46+col] = fmaf(wv2, st[row+4][col+4], su[row*46+col]);
                        }
                    }
                }
            } else if (nt <= 4){
                T4 tf = t4_fwd_dk(stage, n, 54);
                for (int row = ty_; row < 50; row += 8){
                    int gy = Y0 - 9 + row;
                    bool iny = (unsigned)gy < HV;
                    for (int col = tx_; col < 50; col += 32){
                        int gx = X0 - 9 + col;
                        float a2 = 0.f;
                        if (inter || (iny && (unsigned)gx < WV)) a2 = w2*c4(&st[row][col], tf, 0.f);
                        sbuf[row*50+col] = a2;
                    }
                }
                __syncthreads();
                T4 ta = t4_adj_dk(stage, n, 50);
                for (int row = ty_; row < 46; row += 8){
                    int gy = Y0 - 7 + row;
                    bool iny = (unsigned)gy < HV;
                    for (int col = tx_; col < 46; col += 32){
                        int gx = X0 - 7 + col;
                        if (inter || (iny && (unsigned)gx < WV))
                            su[row*46+col] = c4(sbuf + row*50 + col, ta, su[row*46+col]);
                    }
                }
                __syncthreads();
            } else {
                for (int row = ty_; row < 50; row += 8){
                    int gy = Y0 - 9 + row;
                    bool iny = (unsigned)gy < HV;
                    for (int col = tx_; col < 50; col += 32){
                        int gx = X0 - 9 + col;
                        float a2 = 0.f;
                        if (inter || (iny && (unsigned)gx < WV)) a2 = w2*cg_fwd_dk(&st[row][col], stage, n, nt, 54, 0.f);
                        sbuf[row*50+col] = a2;
                    }
                }
                __syncthreads();
                for (int row = ty_; row < 46; row += 8){
                    int gy = Y0 - 7 + row;
                    bool iny = (unsigned)gy < HV;
                    for (int col = tx_; col < 46; col += 32){
                        int gx = X0 - 7 + col;
                        if (inter || (iny && (unsigned)gx < WV))
                            su[row*46+col] = cg_adj_dk(sbuf + row*50 + col, stage, n, nt, 50, su[row*46+col]);
                    }
                }
                __syncthreads();
            }
        }
        __syncthreads();
    }

    float acc[4] = {0,0,0,0};
    int rbase = ty_*4;
    if (fastD){
        for (int v = 0; v < 15; v++){
            float win[18];
            #pragma unroll
            for (int j = 0; j < 18; j++) win[j] = st[rbase+j][tx_+v];
            #pragma unroll
            for (int u = 0; u < 15; u++){
                float kv = sk[u*15+v];
                #pragma unroll
                for (int q = 0; q < 4; q++) acc[q] = fmaf(kv, win[u+q], acc[q]);
            }
        }
        float sc = g_scale1[stage];
        #pragma unroll
        for (int q = 0; q < 4; q++) acc[q] *= sc;
    } else {
        for (int v = 0; v < 15; v++){
            float win[18];
            #pragma unroll
            for (int j = 0; j < 18; j++) win[j] = su[(rbase+j)*46 + tx_+v];
            #pragma unroll
            for (int u = 0; u < 15; u++){
                float kv = sk[u*15+v];
                #pragma unroll
                for (int q = 0; q < 4; q++) acc[q] = fmaf(kv, win[u+q], acc[q]);
            }
        }
        __syncthreads();
    }

    // ---- regularizer term ----
    if (inter && p2){
        int nt4 = g_Snt4[stage];
        #pragma unroll
        for (int q = 0; q < 4; q++){
            const float* base = &sx[rbase+q+4][tx_+4];
            float a2 = acc[q];
            for (int t = 0; t < nt4; t += 4){
                a2 = fmaf(sSv[t],   base[sSo[t]],   a2);
                a2 = fmaf(sSv[t+1], base[sSo[t+1]], a2);
                a2 = fmaf(sSv[t+2], base[sSo[t+2]], a2);
                a2 = fmaf(sSv[t+3], base[sSo[t+3]], a2);
            }
            acc[q] = a2;
        }
        if (csrc){
            const float* cp = csrc + z*NPIX;
            #pragma unroll
            for (int q = 0; q < 4; q++)
                acc[q] -= cp[(Y0+rbase+q)*WV + X0 + tx_];
        }
    } else {
        for (int m = 0; m < 5; m++){
            float wm = rkw[stage*5+m];
            float pm = rpow[stage*5+m];
            float wp = wm*pm;
            int nt = g_rknt[stage][m];
            float* sph = pool + m*1296;
            const float* tg = tgt ? (tgt + (b*5+m)*CN + c*NPIX) : nullptr;
            float* vd = vdst + (b*5+m)*CN + c*NPIX;
            if (nt <= 4){
                T4 tf = t4_fwd_rk(stage, m, 40);
                for (int row = ty_; row < 36; row += 8){
                    int gy = Y0 - 2 + row;
                    bool iny = (unsigned)gy < HV;
                    bool rin = (row >= 2 && row < 34);
                    for (int col = tx_; col < 36; col += 32){
                        int gx = X0 - 2 + col;
                        float ph = 0.f;
                        if (iny && (unsigned)gx < WV){
                            float vv = c4(&sx[row][col], tf, 0.f);
                            int gi = gy*WV + gx;
                            if (tg) vv -= tg[gi];
                            if (p2){
                                ph = wp*sgnf(vv)*(fabsf(vv)+EPSF);
                            } else {
                                ph = wp*sgnf(vv)*powx(fabsf(vv)+EPSF, pm-1.f);
                                if (rin && col >= 2 && col < 34) vd[gi] = vv;
                            }
                        }
                        sph[row*36+col] = ph;
                    }
                }
            } else {
                for (int row = ty_; row < 36; row += 8){
                    int gy = Y0 - 2 + row;
                    bool iny = (unsigned)gy < HV;
                    bool rin = (row >= 2 && row < 34);
                    for (int col = tx_; col < 36; col += 32){
                        int gx = X0 - 2 + col;
                        float ph = 0.f;
                        if (iny && (unsigned)gx < WV){
                            float vv = cg_fwd_rk(&sx[row][col], stage, m, nt, 40, 0.f);
                            int gi = gy*WV + gx;
                            if (tg) vv -= tg[gi];
                            if (p2){
                                ph = wp*sgnf(vv)*(fabsf(vv)+EPSF);
                            } else {
                                ph = wp*sgnf(vv)*powx(fabsf(vv)+EPSF, pm-1.f);
                                if (rin && col >= 2 && col < 34) vd[gi] = vv;
                            }
                        }
                        sph[row*36+col] = ph;
                    }
                }
            }
        }
        __syncthreads();
        for (int m = 0; m < 5; m++){
            int nt = g_rknt[stage][m];
            const float* sph = pool + m*1296;
            if (nt <= 4){
                T4 ta = t4_adj_rk(stage, m, 36);
                #pragma unroll
                for (int q = 0; q < 4; q++)
                    acc[q] = c4(sph + (rbase+q)*36 + tx_, ta, acc[q]);
            } else {
                for (int q = 0; q < 4; q++)
                    acc[q] = cg_adj_rk(sph + (rbase+q)*36 + tx_, stage, m, nt, 36, acc[q]);
            }
        }
    }

    float* ro = rdst + z*NPIX;
    float ss = 0.f;
    #pragma unroll
    for (int q = 0; q < 4; q++){
        ro[(Y0+rbase+q)*WV + X0 + tx_] = -acc[q];
        ss = fmaf(acc[q], acc[q], ss);
    }
    __syncthreads();
    sh[tid] = ss; __syncthreads();
    for (int o = 128; o; o >>= 1){ if (tid < o) sh[tid] += sh[tid+o]; __syncthreads(); }
    if (tid == 0) g_partR[b*768 + c*256 + blockIdx.y*16 + blockIdx.x] = sh[0];
}

// ---------------- prior targets + c-term ----------------
__global__ void __launch_bounds__(256)
k_prior(const float* __restrict__ xsrc, float* __restrict__ dst, float* __restrict__ cdst,
        const float* __restrict__ thr,
        const float* __restrict__ rkw, const float* __restrict__ rpow, int stage)
{
    int z = blockIdx.z; int b = z/CV, c = z - b*CV;
    __shared__ float sxx[1600];
    __shared__ float pool[6480];
    int tx_ = threadIdx.x, ty_ = threadIdx.y;
    int tid = ty_*32 + tx_;
    int X0 = blockIdx.x*32, Y0 = blockIdx.y*32;
    const float* xp = xsrc + z*NPIX;
    for (int row = ty_; row < 40; row += 8){
        int gy = Y0-4+row;
        bool iny = (unsigned)gy < HV;
        for (int col = tx_; col < 40; col += 32){
            int gx = X0-4+col;
            sxx[row*40+col] = (iny && (unsigned)gx < WV) ? xp[gy*WV+gx] : 0.f;
        }
    }
    __syncthreads();
    int rbase = ty_*4;
    int gxo = X0 + tx_;
    for (int m = 0; m < 5; m++){
        int nt = g_rknt[stage][m];
        float th = thr[m];
        float wp = rkw[stage*5+m]*rpow[stage*5+m];
        float* sph = pool + m*1296;
        T4 tf = t4_fwd_rk(stage, m, 40);
        for (int row = ty_; row < 36; row += 8){
            int gy = Y0-2+row;
            bool iny = (unsigned)gy < HV;
            bool rin = (row >= 2 && row < 34);
            for (int col = tx_; col < 36; col += 32){
                int gx = X0-2+col;
                float shr = 0.f;
                if (iny && (unsigned)gx < WV){
                    float v;
                    if (nt <= 4) v = c4(&sxx[row*40+col], tf, 0.f);
                    else v = cg_fwd_rk(&sxx[row*40+col], stage, m, nt, 40, 0.f);
                    shr = sgnf(v)*fmaxf(fabsf(v)-th, 0.f);
                    if (rin && col >= 2 && col < 34)
                        dst[(b*5+m)*CN + c*NPIX + gy*WV + gx] = shr;
                }
                sph[row*36+col] = wp*shr;
            }
        }
    }
    __syncthreads();
    float cacc[4] = {0,0,0,0};
    for (int m = 0; m < 5; m++){
        int nt = g_rknt[stage][m];
        const float* sph = pool + m*1296;
        if (nt <= 4){
            T4 ta = t4_adj_rk(stage, m, 36);
            #pragma unroll
            for (int q = 0; q < 4; q++)
                cacc[q] = c4(sph + (rbase+q)*36 + tx_, ta, cacc[q]);
        } else {
            for (int q = 0; q < 4; q++)
                cacc[q] = cg_adj_rk(sph + (rbase+q)*36 + tx_, stage, m, nt, 36, cacc[q]);
        }
    }
    #pragma unroll
    for (int q = 0; q < 4; q++)
        cdst[z*NPIX + (Y0+rbase+q)*WV + gxo] = cacc[q];
}

// ---------------- bilateral grid (coalesced splat, folded x+alpha*p) ----------------
__global__ void __launch_bounds__(256)
k_splat(const float* __restrict__ x, const float* __restrict__ p,
        float* __restrict__ grid, int slot){
    int pcgy = blockIdx.x;
    int gy = pcgy & 63;
    int pc = pcgy >> 6;
    int b = pc / CV;
    int tid = threadIdx.x;
    __shared__ float srow[4096];
    __shared__ float sh[256], sh2[256], s_alpha;
    float al = alpha_reduce(b, slot, tid, sh, sh2, &s_alpha);
    const float* xp = x + pc*NPIX + (gy*8)*WV;
    const float* pq = p + pc*NPIX + (gy*8)*WV;
    for (int i = tid; i < 4096; i += 256) srow[i] = fmaf(al, pq[i], xp[i]);
    __syncthreads();
    if (tid < 64){
        int gx = tid;
        float bv[NBIN], bw[NBIN];
        #pragma unroll
        for (int z = 0; z < NBIN; z++){ bv[z] = 0.f; bw[z] = 0.f; }
        for (int dy = 0; dy < 8; dy++)
            for (int dx = 0; dx < 8; dx++){
                float I = srow[dy*512 + gx*8+dx];
                float Ic = fminf(fmaxf(I, 0.f), 1.f);
                int zi = (int)rintf(Ic * (float)(NBIN-1));
                zi = max(0, min(NBIN-1, zi));
                bv[zi] += Ic; bw[zi] += 1.f;
            }
        float* gp = grid + ((long)pcgy*64 + gx)*NBIN*2;
        #pragma unroll
        for (int z = 0; z < NBIN; z++){ gp[z*2] = bv[z]; gp[z*2+1] = bw[z]; }
    }
}

// fused separable grid filter: y-conv (11) -> x-conv (11) -> z-conv (5), one launch.
// block = (pc, 8x8 cell tile); zero-padding == reference's range check (fmaf(f,0,s)==s).
__global__ void __launch_bounds__(256)
k_bconv(const float* __restrict__ gin, float* __restrict__ gout,
        const float* __restrict__ fs, const float* __restrict__ fr)
{
    int blk = blockIdx.x;
    int txt = blk & 7; int tyt = (blk >> 3) & 7; int pc = blk >> 6;
    int Y0 = tyt*8, X0 = txt*8;
    __shared__ float sin[18*18*18];   // [row][col][k], k = z*2+ch
    __shared__ float sy [8*18*18];
    __shared__ float sxz[8*8*18];
    __shared__ float sfs[11], sfr[5];
    int tid = threadIdx.x;
    const float* gp = gin + (long)pc*(GH*GW*NBIN*2);
    for (int i = tid; i < 18*18*18; i += 256){
        int k = i % 18; int rc = i / 18;
        int c0 = rc % 18, r0 = rc / 18;
        int gy = Y0 - 5 + r0, gx = X0 - 5 + c0;
        float v = 0.f;
        if ((unsigned)gy < GH && (unsigned)gx < GW)
            v = gp[(gy*GW + gx)*18 + k];
        sin[i] = v;
    }
    if (tid < 11) sfs[tid] = fs[tid];
    if (tid < 5)  sfr[tid] = fr[tid];
    __syncthreads();
    // y-conv: rows 0..7 (out), cols 0..17, k 0..17
    for (int i = tid; i < 8*18*18; i += 256){
        int k = i % 18; int rc = i / 18;
        int c0 = rc % 18, r0 = rc / 18;
        const float* bp = sin + (r0*18 + c0)*18 + k;
        float s = 0.f;
        #pragma unroll
        for (int t = 0; t < 11; t++) s = fmaf(sfs[t], bp[t*324], s);
        sy[i] = s;
    }
    __syncthreads();
    // x-conv: rows 0..7, cols 0..7, k 0..17
    for (int i = tid; i < 8*8*18; i += 256){
        int k = i % 18; int rc = i / 18;
        int c0 = rc % 8, r0 = rc / 8;
        const float* bp = sy + (r0*18 + c0)*18 + k;
        float s = 0.f;
        #pragma unroll
        for (int t = 0; t < 11; t++) s = fmaf(sfs[t], bp[t*18], s);
        sxz[i] = s;
    }
    __syncthreads();
    // z-conv: 5 taps over NBIN=9, per channel
    float* go = gout + (long)pc*(GH*GW*NBIN*2);
    for (int i = tid; i < 8*8*18; i += 256){
        int k = i % 18; int rc = i / 18;
        int ch = k & 1; int zz = k >> 1;
        const float* bp = sxz + rc*18 + ch;
        float s = 0.f;
        #pragma unroll
        for (int t = 0; t < 5; t++){
            int cc = zz + t - 2;
            if ((unsigned)cc < NBIN) s = fmaf(sfr[t], bp[cc*2], s);
        }
        int r0 = rc / 8, c0 = rc % 8;
        go[((Y0+r0)*GW + X0+c0)*18 + k] = s;
    }
}

// slice with folded x+alpha*p input; writes result to xout
__global__ void k_slice(const float* __restrict__ xsrc, const float* __restrict__ psrc,
                        float* __restrict__ xout, const float* __restrict__ grid, int slot){
    int i = blockIdx.x*blockDim.x + threadIdx.x;
    int tid = threadIdx.x;
    int pc = i / NPIX;
    int b = pc / CV;
    __shared__ float sh[256], sh2[256], s_alpha;
    float al = alpha_reduce(b, slot, tid, sh, sh2, &s_alpha);
    if (i >= BCN) return;
    int pix = i - pc*NPIX;
    int y = pix / WV, xx = pix - y*WV;
    float I = fmaf(al, psrc[i], xsrc[i]);
    float Ic = fminf(fmaxf(I, 0.f), 1.f);
    float yf = (float)y * 0.125f;
    float xf = (float)xx * 0.125f;
    float zf = Ic * (float)(NBIN-1);
    int y0 = max(0, min(GH-1, (int)floorf(yf)));  int y1 = min(y0+1, GH-1);
    float wy = fminf(fmaxf(yf - (float)y0, 0.f), 1.f);
    int x0 = max(0, min(GW-1, (int)floorf(xf)));  int x1 = min(x0+1, GW-1);
    float wx = fminf(fmaxf(xf - (float)x0, 0.f), 1.f);
    int z0 = max(0, min(NBIN-1, (int)floorf(zf))); int z1 = min(z0+1, NBIN-1);
    float wz = fminf(fmaxf(zf - (float)z0, 0.f), 1.f);
    const float* gp = grid + (long)pc*GH*GW*NBIN*2;
    float a0 = 0.f, a1 = 0.f;
    int ys[2]   = {y0, y1};  float wys[2] = {1.f-wy, wy};
    int xs[2]   = {x0, x1};  float wxs[2] = {1.f-wx, wx};
    int zs[2]   = {z0, z1};  float wzs[2] = {1.f-wz, wz};
    for (int a = 0; a < 2; a++)
        for (int bb = 0; bb < 2; bb++)
            for (int cc = 0; cc < 2; cc++){
                float w = wys[a]*wxs[bb]*wzs[cc];
                int idx = (((ys[a]*GW) + xs[bb])*NBIN + zs[cc])*2;
                a0 = fmaf(w, gp[idx], a0);
                a1 = fmaf(w, gp[idx+1], a1);
            }
    xout[i] = a0 / (a1 + 1e-8f);
}

// ---------------- host orchestration ----------------
extern "C" void kernel_launch(void* const* d_in, const int* in_sizes, int n_in,
                              void* d_out, int out_size)
{
    const float* blurred = (const float*)d_in[0];
    const float* kern    = (const float*)d_in[1];
    const float* dks     = (const float*)d_in[2];
    const float* dkw     = (const float*)d_in[3];
    const float* rks     = (const float*)d_in[4];
    const float* rkw     = (const float*)d_in[5];
    const float* rpow    = (const float*)d_in[6];
    const float* fs      = (const float*)d_in[7];
    const float* fr      = (const float*)d_in[8];
    const float* thr     = (const float*)d_in[9];
    const int NCG = 5;

    float *px, *px2, *pr, *pp, *pp2, *pt, *pt2, *ptp, *pv, *ptg, *pgA, *pgB;
    cudaGetSymbolAddress((void**)&px,  g_x);
    cudaGetSymbolAddress((void**)&px2, g_x2);
    cudaGetSymbolAddress((void**)&pr,  g_r);
    cudaGetSymbolAddress((void**)&pp,  g_p);
    cudaGetSymbolAddress((void**)&pp2, g_p2);
    cudaGetSymbolAddress((void**)&pt,  g_t);
    cudaGetSymbolAddress((void**)&pt2, g_t2);
    cudaGetSymbolAddress((void**)&ptp, g_tp);
    cudaGetSymbolAddress((void**)&pv,  g_v);
    cudaGetSymbolAddress((void**)&ptg, g_tgt);
    cudaGetSymbolAddress((void**)&pgA, g_gridA);
    cudaGetSymbolAddress((void**)&pgB, g_gridB);

    dim3 cb(32, 8);
    dim3 cg15(16, 8, BV*CV);
    dim3 cg32(16, 16, BV*CV);
    int EW = (BCN + 255)/256;

    k_prep<<<1,32>>>(dks, dkw, rks, rkw, rpow);

    const float* s0x = nullptr; const float* s0p = nullptr; int s0slot = 0;
    auto cgrun = [&](int stage, const float* tgt, const float* cbuf,
                     const float* xin, float* xfinal){
        float* tcur = pt;   float* tnxt = pt2;
        float* pcur = pp;   float* pnxt = pp2;
        k_conv15<<<cg15,cb>>>(xin, tcur, kern, blurred);
        float* xcur = (xin == px) ? px2 : px;
        k_gradfull<<<cg32,cb>>>(xin, pcur, tcur, ptp, xcur, tnxt, tgt, cbuf, pr, pv,
                                kern, rkw, rpow, stage, 0, 1);
        { float* q = tcur; tcur = tnxt; tnxt = q; }
        for (int it = 0; it < NCG; it++){
            int rs = it & 1, ws = rs ^ 1;
            k_pstep<<<cg15,cb>>>(pcur, pnxt, ptp, pr, kern, rkw, rpow, stage, it == 0, rs);
            if (it == NCG-1){
                if (xfinal){
                    k_axpy_final<<<dim3(256,BV),256>>>(xcur, pnxt, xfinal, ws);
                } else {
                    s0x = xcur; s0p = pnxt; s0slot = ws;
                }
            } else {
                float* xd = (xcur == px) ? px2 : px;
                k_gradfull<<<cg32,cb>>>(xcur, pnxt, tcur, ptp, xd, tnxt, tgt, cbuf, pr, pv,
                                        kern, rkw, rpow, stage, ws, 0);
                xcur = xd;
                { float* q = tcur; tcur = tnxt; tnxt = q; }
            }
            { float* q = pcur; pcur = pnxt; pnxt = q; }
        }
    };

    // Stage 0 (targets = 0, c = 0); final axpy deferred into splat/slice
    cgrun(0, nullptr, nullptr, blurred, nullptr);

    float* xbi = (s0x == px) ? px2 : px;
    k_splat<<<BV*CV*GH, 256>>>(s0x, s0p, pgA, s0slot);
    k_bconv<<<BV*CV*64, 256>>>(pgA, pgB, fs, fr);
    k_slice<<<EW,256>>>(s0x, s0p, xbi, pgB, s0slot);

    k_prior<<<cg32,cb>>>(xbi, ptg, pv, thr, rkw, rpow, 1);
    cgrun(1, ptg, pv, xbi, (float*)d_out);
}

// round 15
// speedup vs baseline: 1.0713x; 1.0713x over previous
#include <cuda_runtime.h>

#define BV 2
#define CV 3
#define HV 512
#define WV 512
#define NPIX (HV*WV)
#define CN (CV*NPIX)
#define BCN (BV*CN)
#define GH 64
#define GW 64
#define NBIN 9
#define NGRID (BV*CV*GH*GW*NBIN*2)
#define EPSF 1e-8f
#define CG_TOL 1e-4f

// ---------------- scratch (device globals; no allocation) ----------------
__device__ float g_x[BCN], g_x2[BCN];
__device__ float g_r[BCN];
__device__ float g_p[BCN], g_p2[BCN];
__device__ float g_t[BCN], g_t2[BCN];
__device__ float g_tp[BCN];
__device__ float g_v[BV*5*CN];        // reused: [0..BCN) holds c-term for stage 1
__device__ float g_tgt[BV*5*CN];
__device__ float g_gridA[NGRID], g_gridB[NGRID];
__device__ float g_partN[BV*384];
__device__ float g_partDf[BV*384];
__device__ float g_partR[BV*768];
__device__ float g_r0[BV];
__device__ float g_rnS[2][BV];
__device__ int   g_doneS[2][BV];

// sparse tap metadata, zero-padded (exact: fmaf(0,x,a)==a for finite x)
__device__ int   g_dknt[2][6];
__device__ int   g_dkdy[2][6][25];
__device__ int   g_dkdx[2][6][25];
__device__ float g_dkv [2][6][25];
__device__ float g_dkw2[2][6];
__device__ int   g_rknt[2][5];
__device__ int   g_rkdy[2][5][25];
__device__ int   g_rkdx[2][5][25];
__device__ float g_rkv [2][5][25];
__device__ int   g_fastDk[2];
__device__ float g_scale1[2];
__device__ int   g_allp2[2];
__device__ int   g_fusedDen[2];
__device__ int   g_Snt4[2];
__device__ float g_Sv[2][84];
__device__ int   g_So40[2][84];

__device__ __forceinline__ float powx(float a, float e){
    if (e == 0.0f) return 1.0f;
    if (e == 1.0f) return a;
    return powf(a, e);
}
__device__ __forceinline__ float sgnf(float v){
    return (v > 0.f) ? 1.f : ((v < 0.f) ? -1.f : 0.f);
}

struct T4 { float v0,v1,v2,v3; int o0,o1,o2,o3; };
__device__ __forceinline__ T4 t4_fwd_rk(int s,int m,int st){
    T4 t;
    t.v0=g_rkv[s][m][0]; t.v1=g_rkv[s][m][1]; t.v2=g_rkv[s][m][2]; t.v3=g_rkv[s][m][3];
    t.o0=g_rkdy[s][m][0]*st+g_rkdx[s][m][0]; t.o1=g_rkdy[s][m][1]*st+g_rkdx[s][m][1];
    t.o2=g_rkdy[s][m][2]*st+g_rkdx[s][m][2]; t.o3=g_rkdy[s][m][3]*st+g_rkdx[s][m][3];
    return t;
}
__device__ __forceinline__ T4 t4_adj_rk(int s,int m,int st){
    T4 t;
    t.v0=g_rkv[s][m][0]; t.v1=g_rkv[s][m][1]; t.v2=g_rkv[s][m][2]; t.v3=g_rkv[s][m][3];
    t.o0=(4-g_rkdy[s][m][0])*st+(4-g_rkdx[s][m][0]); t.o1=(4-g_rkdy[s][m][1])*st+(4-g_rkdx[s][m][1]);
    t.o2=(4-g_rkdy[s][m][2])*st+(4-g_rkdx[s][m][2]); t.o3=(4-g_rkdy[s][m][3])*st+(4-g_rkdx[s][m][3]);
    return t;
}
__device__ __forceinline__ T4 t4_fwd_dk(int s,int n,int st){
    T4 t;
    t.v0=g_dkv[s][n][0]; t.v1=g_dkv[s][n][1]; t.v2=g_dkv[s][n][2]; t.v3=g_dkv[s][n][3];
    t.o0=g_dkdy[s][n][0]*st+g_dkdx[s][n][0]; t.o1=g_dkdy[s][n][1]*st+g_dkdx[s][n][1];
    t.o2=g_dkdy[s][n][2]*st+g_dkdx[s][n][2]; t.o3=g_dkdy[s][n][3]*st+g_dkdx[s][n][3];
    return t;
}
__device__ __forceinline__ T4 t4_adj_dk(int s,int n,int st){
    T4 t;
    t.v0=g_dkv[s][n][0]; t.v1=g_dkv[s][n][1]; t.v2=g_dkv[s][n][2]; t.v3=g_dkv[s][n][3];
    t.o0=(4-g_dkdy[s][n][0])*st+(4-g_dkdx[s][n][0]); t.o1=(4-g_dkdy[s][n][1])*st+(4-g_dkdx[s][n][1]);
    t.o2=(4-g_dkdy[s][n][2])*st+(4-g_dkdx[s][n][2]); t.o3=(4-g_dkdy[s][n][3])*st+(4-g_dkdx[s][n][3]);
    return t;
}
__device__ __forceinline__ float c4(const float* p, const T4& t, float a){
    a = fmaf(t.v0, p[t.o0], a);
    a = fmaf(t.v1, p[t.o1], a);
    a = fmaf(t.v2, p[t.o2], a);
    a = fmaf(t.v3, p[t.o3], a);
    return a;
}
__device__ __forceinline__ float cg_fwd_dk(const float* p,int s,int n,int nt,int st,float a){
    for (int t = 0; t < nt; t++) a = fmaf(g_dkv[s][n][t], p[g_dkdy[s][n][t]*st+g_dkdx[s][n][t]], a);
    return a;
}
__device__ __forceinline__ float cg_adj_dk(const float* p,int s,int n,int nt,int st,float a){
    for (int t = 0; t < nt; t++) a = fmaf(g_dkv[s][n][t], p[(4-g_dkdy[s][n][t])*st+(4-g_dkdx[s][n][t])], a);
    return a;
}
__device__ __forceinline__ float cg_fwd_rk(const float* p,int s,int m,int nt,int st,float a){
    for (int t = 0; t < nt; t++) a = fmaf(g_rkv[s][m][t], p[g_rkdy[s][m][t]*st+g_rkdx[s][m][t]], a);
    return a;
}
__device__ __forceinline__ float cg_adj_rk(const float* p,int s,int m,int nt,int st,float a){
    for (int t = 0; t < nt; t++) a = fmaf(g_rkv[s][m][t], p[(4-g_rkdy[s][m][t])*st+(4-g_rkdx[s][m][t])], a);
    return a;
}
__device__ __forceinline__ float alpha_reduce(int b, int slot, int tid,
                                              float* sh, float* sh2, float* s_alpha)
{
    float sn = 0.f, sd = 0.f;
    if (tid < 128){
        sn = g_partN [b*384+tid] + g_partN [b*384+128+tid] + g_partN [b*384+256+tid];
        sd = g_partDf[b*384+tid] + g_partDf[b*384+128+tid] + g_partDf[b*384+256+tid];
    }
    sh[tid] = sn; sh2[tid] = sd; __syncthreads();
    for (int o = 128; o; o >>= 1){
        if (tid < o){ sh[tid] += sh[tid+o]; sh2[tid] += sh2[tid+o]; }
        __syncthreads();
    }
    if (tid == 0){
        int dn = g_doneS[slot][b];
        *s_alpha = dn ? 0.f : sh[0]/(sh2[0] + 1e-12f);
    }
    __syncthreads();
    return *s_alpha;
}

// ---------------- prep ----------------
__global__ void k_prep(const float* __restrict__ dks, const float* __restrict__ dkw,
                       const float* __restrict__ rks, const float* __restrict__ rkw,
                       const float* __restrict__ rpow)
{
    if (threadIdx.x != 0 || blockIdx.x != 0) return;
    for (int s = 0; s < 2; s++){
        int fast = 1, center1 = 1; float sc1 = 0.f;
        for (int n = 0; n < 6; n++){
            float w2 = 2.f*dkw[s*6+n];
            g_dkw2[s][n] = w2;
            int cnt = 0;
            for (int j = 0; j < 25; j++){
                float v = dks[(s*6+n)*25 + j];
                if (v != 0.f){
                    g_dkdy[s][n][cnt] = j/5; g_dkdx[s][n][cnt] = j%5;
                    g_dkv [s][n][cnt] = v; cnt++;
                }
            }
            g_dknt[s][n] = cnt;
            for (int j = cnt; j < 25; j++){ g_dkdy[s][n][j]=0; g_dkdx[s][n][j]=0; g_dkv[s][n][j]=0.f; }
            if (w2 != 0.f){
                if (cnt == 1){
                    sc1 += w2*g_dkv[s][n][0]*g_dkv[s][n][0];
                    if (g_dkdy[s][n][0] != 2 || g_dkdx[s][n][0] != 2) center1 = 0;
                } else { fast = 0; center1 = 0; }
            }
        }
        g_fastDk[s] = fast;
        g_scale1[s] = sc1;
        int p2 = 1;
        for (int m = 0; m < 5; m++){
            if (rpow[s*5+m] != 2.0f) p2 = 0;
            int cnt = 0;
            for (int j = 0; j < 25; j++){
                float v = rks[(s*5+m)*25 + j];
                if (v != 0.f){
                    g_rkdy[s][m][cnt] = j/5; g_rkdx[s][m][cnt] = j%5;
                    g_rkv [s][m][cnt] = v; cnt++;
                }
            }
            g_rknt[s][m] = cnt;
            for (int j = cnt; j < 25; j++){ g_rkdy[s][m][j]=0; g_rkdx[s][m][j]=0; g_rkv[s][m][j]=0.f; }
        }
        g_allp2[s] = p2;
        g_fusedDen[s] = p2 && center1;

        float Sbuf[81];
        for (int j = 0; j < 81; j++) Sbuf[j] = 0.f;
        for (int m = 0; m < 5; m++){
            float wp = rkw[s*5+m]*rpow[s*5+m];
            int nt = g_rknt[s][m];
            for (int t1 = 0; t1 < nt; t1++)
                for (int t2 = 0; t2 < nt; t2++){
                    int ody = g_rkdy[s][m][t1] - g_rkdy[s][m][t2];
                    int odx = g_rkdx[s][m][t1] - g_rkdx[s][m][t2];
                    Sbuf[(ody+4)*9 + (odx+4)] += wp*g_rkv[s][m][t1]*g_rkv[s][m][t2];
                }
        }
        int cnt = 0;
        for (int j = 0; j < 81; j++){
            if (Sbuf[j] != 0.f){
                g_Sv[s][cnt] = Sbuf[j];
                g_So40[s][cnt] = (j/9 - 4)*40 + (j%9 - 4);
                cnt++;
            }
        }
        while (cnt & 3){ g_Sv[s][cnt] = 0.f; g_So40[s][cnt] = 0; cnt++; }
        g_Snt4[s] = cnt;
    }
}

// ---------------- plain 15x15 conv - sub (CG init only), 32x64 tile ----------------
__global__ void __launch_bounds__(256)
k_conv15(const float* __restrict__ src, float* __restrict__ dst,
         const float* __restrict__ kern, const float* __restrict__ sub)
{
    int z = blockIdx.z; int b = z / CV;
    __shared__ float tile[78][46];
    __shared__ float sk[225];
    const float* sp = src + z*NPIX;
    int X0 = blockIdx.x*32, Y0 = blockIdx.y*64;
    int x0 = X0 - 7, y0 = Y0 - 7;
    int tx_ = threadIdx.x, ty_ = threadIdx.y;
    int tid = ty_*32 + tx_;
    bool inter = (Y0 >= 7) && (Y0 + 71 <= HV) && (X0 >= 7) && (X0 + 39 <= WV);
    if (inter){
        for (int row = ty_; row < 78; row += 8){
            const float* rp = sp + (y0+row)*WV + x0;
            for (int col = tx_; col < 46; col += 32) tile[row][col] = rp[col];
        }
    } else {
        for (int row = ty_; row < 78; row += 8){
            int gy = y0 + row;
            bool iny = (unsigned)gy < HV;
            for (int col = tx_; col < 46; col += 32){
                int gx = x0 + col;
                tile[row][col] = (iny && (unsigned)gx < WV) ? sp[gy*WV+gx] : 0.f;
            }
        }
    }
    const float* kb = kern + b*225;
    for (int i = tid; i < 225; i += 256) sk[i] = kb[i];
    __syncthreads();
    float acc[8] = {0,0,0,0,0,0,0,0};
    int rbase = ty_*8;
    for (int v = 0; v < 15; v++){
        float win[22];
        #pragma unroll
        for (int j = 0; j < 22; j++) win[j] = tile[rbase+j][tx_+v];
        #pragma unroll
        for (int u = 0; u < 15; u++){
            float kv = sk[u*15+v];
            #pragma unroll
            for (int q = 0; q < 8; q++) acc[q] = fmaf(kv, win[u+q], acc[q]);
        }
    }
    int gx = X0 + tx_;
    int gyb = Y0 + rbase;
    #pragma unroll
    for (int q = 0; q < 8; q++){
        int oi = z*NPIX + (gyb+q)*WV + gx;
        float o = acc[q];
        if (sub) o -= sub[oi];
        dst[oi] = o;
    }
}

// ---- fused: beta/done + p update + Kp conv + num partial + den partial --------------
__global__ void __launch_bounds__(256,6)
k_pstep(const float* __restrict__ pold, float* __restrict__ pnew,
        float* __restrict__ kp, const float* __restrict__ rsrc,
        const float* __restrict__ kern,
        const float* __restrict__ rkw, const float* __restrict__ rpow,
        int stage, int first, int slot)
{
    int z = blockIdx.z; int b = z/CV, c = z - b*CV;
    int tx_ = threadIdx.x, ty_ = threadIdx.y;
    int tid = ty_*32 + tx_;
    __shared__ float pn[78][46];
    __shared__ float sk[225];
    __shared__ float sh[256];
    __shared__ float sh2[256];
    __shared__ float s_beta;
    __shared__ int s_freeze;

    float a = g_partR[b*768+tid] + g_partR[b*768+256+tid] + g_partR[b*768+512+tid];
    sh[tid] = a; __syncthreads();
    for (int o = 128; o; o >>= 1){ if (tid < o) sh[tid] += sh[tid+o]; __syncthreads(); }
    if (tid == 0){
        float nrn = sh[0];
        int done_prev = first ? 0 : g_doneS[slot][b];
        float rn_prev = first ? 1.f : g_rnS[slot][b];
        float r0 = first ? nrn : g_r0[b];
        int conv_now = (!first) && (nrn < CG_TOL*r0);
        s_beta = first ? 0.f : nrn/(rn_prev + 1e-20f);
        s_freeze = first ? 0 : (done_prev | conv_now);
        if (blockIdx.x == 0 && blockIdx.y == 0 && c == 0){
            g_doneS[slot^1][b] = done_prev | conv_now;
            g_rnS[slot^1][b] = done_prev ? rn_prev : nrn;
            if (first) g_r0[b] = nrn;
        }
    }
    __syncthreads();
    int X0 = blockIdx.x*32, Y0 = blockIdx.y*64;
    if (s_freeze){
        const float* pop = pold + z*NPIX;
        float* pno = pnew + z*NPIX;
        for (int row = ty_; row < 64; row += 8){
            int gi = (Y0+row)*WV + X0 + tx_;
            pno[gi] = pop[gi];
        }
        return;
    }
    float beta = s_beta;
    const float* rp = rsrc + z*NPIX;
    const float* pop = pold + z*NPIX;
    float* pno = pnew + z*NPIX;
    int x0 = X0 - 7, y0 = Y0 - 7;
    bool inter = (Y0 >= 7) && (Y0 + 71 <= HV) && (X0 >= 7) && (X0 + 39 <= WV);
    float s = 0.f;
    if (inter){
        for (int row = ty_; row < 78; row += 8){
            const float* rr = rp + (y0+row)*WV + x0;
            const float* pr2 = pop + (y0+row)*WV + x0;
            float* pw = pno + (y0+row)*WV + x0;
            bool rin = (row >= 7 && row < 71);
            for (int col = tx_; col < 46; col += 32){
                float rv = rr[col];
                float v = first ? rv : fmaf(beta, pr2[col], rv);
                if (rin && col >= 7 && col < 39){
                    pw[col] = v;
                    s = fmaf(rv, v, s);
                }
                pn[row][col] = v;
            }
        }
    } else {
        for (int row = ty_; row < 78; row += 8){
            int gy = y0 + row;
            bool iny = (unsigned)gy < HV;
            bool rin = (row >= 7 && row < 71);
            for (int col = tx_; col < 46; col += 32){
                int gx = x0 + col;
                float v = 0.f;
                if (iny && (unsigned)gx < WV){
                    int gi = gy*WV + gx;
                    float rv = rp[gi];
                    v = first ? rv : fmaf(beta, pop[gi], rv);
                    if (rin && col >= 7 && col < 39){
                        pno[gi] = v;
                        s = fmaf(rv, v, s);
                    }
                }
                pn[row][col] = v;
            }
        }
    }
    const float* kb = kern + b*225;
    for (int i = tid; i < 225; i += 256) sk[i] = kb[i];
    __syncthreads();
    float acc[8] = {0,0,0,0,0,0,0,0};
    int rbase = ty_*8;
    for (int v = 0; v < 15; v++){
        float win[22];
        #pragma unroll
        for (int j = 0; j < 22; j++) win[j] = pn[rbase+j][tx_+v];
        #pragma unroll
        for (int u = 0; u < 15; u++){
            float kv = sk[u*15+v];
            #pragma unroll
            for (int q = 0; q < 8; q++) acc[q] = fmaf(kv, win[u+q], acc[q]);
        }
    }
    float* ko = kp + z*NPIX;
    #pragma unroll
    for (int q = 0; q < 8; q++)
        ko[(Y0+rbase+q)*WV + X0 + tx_] = acc[q];

    float sden = 0.f;
    {
        float sc1 = g_scale1[stage];
        #pragma unroll
        for (int q = 0; q < 8; q++) sden = fmaf(sc1*acc[q], acc[q], sden);
        for (int m = 0; m < 5; m++){
            int nt = g_rknt[stage][m];
            float pmv = rpow[stage*5+m];
            float wc = rkw[stage*5+m]*pmv*(pmv-1.f);
            if (nt <= 4){
                T4 tf = t4_fwd_rk(stage, m, 46);
                #pragma unroll
                for (int q = 0; q < 8; q++){
                    float rv = c4(&pn[rbase+q+5][tx_+5], tf, 0.f);
                    sden = fmaf(wc*rv, rv, sden);
                }
            } else {
                for (int q = 0; q < 8; q++){
                    float rv = cg_fwd_rk(&pn[rbase+q+5][tx_+5], stage, m, nt, 46, 0.f);
                    sden = fmaf(wc*rv, rv, sden);
                }
            }
        }
    }
    __syncthreads();
    sh[tid] = s; sh2[tid] = sden; __syncthreads();
    for (int o = 128; o; o >>= 1){
        if (tid < o){ sh[tid] += sh[tid+o]; sh2[tid] += sh2[tid+o]; }
        __syncthreads();
    }
    if (tid == 0){
        g_partN [b*384 + c*128 + blockIdx.y*16 + blockIdx.x] = sh[0];
        g_partDf[b*384 + c*128 + blockIdx.y*16 + blockIdx.x] = sh2[0];
    }
}

// ---------------- final-iteration axpy (stage 1 only) ----------------
__global__ void k_axpy_final(const float* __restrict__ xsrc, const float* __restrict__ psrc,
                             float* __restrict__ xdst, int slot)
{
    int b = blockIdx.y;
    int tid = threadIdx.x;
    __shared__ float sh[256], sh2[256], s_alpha;
    float al = alpha_reduce(b, slot, tid, sh, sh2, &s_alpha);
    const float* xp = xsrc + b*CN;
    const float* pp = psrc + b*CN;
    float* xo = xdst + b*CN;
    for (int i = blockIdx.x*256 + tid; i < CN; i += 65536)
        xo[i] = fmaf(al, pp[i], xp[i]);
}

// ---------------- fused gradient + x/t update + r-norm partial ----------------
__global__ void __launch_bounds__(256,5)
k_gradfull(const float* __restrict__ xsrc, const float* __restrict__ psrc,
           const float* __restrict__ tsrc, const float* __restrict__ tpsrc,
           float* __restrict__ xdst, float* __restrict__ tdst,
           const float* __restrict__ tgt, const float* __restrict__ csrc,
           float* __restrict__ rdst, float* __restrict__ vdst,
           const float* __restrict__ kern,
           const float* __restrict__ rkw, const float* __restrict__ rpow,
           int stage, int slot, int first)
{
    int z = blockIdx.z; int b = z/CV, c = z - b*CV;
    int tx_ = threadIdx.x, ty_ = threadIdx.y;
    int tid = ty_*32 + tx_;
    int X0 = blockIdx.x*32, Y0 = blockIdx.y*32;

    int dn = first ? 0 : g_doneS[slot][b];
    if (dn){
        const float* xp = xsrc + z*NPIX;
        const float* tp = tsrc + z*NPIX;
        float* xo = xdst + z*NPIX;
        float* to = tdst + z*NPIX;
        for (int row = ty_; row < 32; row += 8){
            int gi = (Y0+row)*WV + X0 + tx_;
            xo[gi] = xp[gi];
            to[gi] = tp[gi];
        }
        return;
    }

    __shared__ float st[54][54];
    __shared__ float sx[40][40];
    __shared__ float pool[6480];
    __shared__ float sk[225];
    __shared__ float sSv[84];
    __shared__ int   sSo[84];
    __shared__ float sh[256];
    __shared__ float sh2[256];
    __shared__ float s_alpha;

    if (first){
        if (tid == 0) s_alpha = 0.f;
        __syncthreads();
    } else {
        alpha_reduce(b, slot, tid, sh, sh2, &s_alpha);
    }
    float al = s_alpha;

    const float* xp = xsrc + z*NPIX;
    const float* pp = psrc + z*NPIX;
    const float* tp = tsrc + z*NPIX;
    const float* tq = tpsrc + z*NPIX;
    float* xo = xdst + z*NPIX;
    float* to = tdst + z*NPIX;

    bool inter = (Y0 >= 11) && (Y0 + 43 <= HV) && (X0 >= 11) && (X0 + 43 <= WV);
    bool fastD = inter && (g_fastDk[stage] != 0);
    int p2 = g_allp2[stage];
    float* su = pool;
    float* sbuf = pool + 2116;

    if (fastD){
        for (int row = ty_; row < 46; row += 8){
            const float* a1 = tp + (Y0-7+row)*WV + X0-7;
            const float* a2 = tq + (Y0-7+row)*WV + X0-7;
            float* a3 = to + (Y0-7+row)*WV + X0-7;
            bool rin = (row >= 7 && row < 39);
            for (int col = tx_; col < 46; col += 32){
                float v = first ? a1[col] : fmaf(al, a2[col], a1[col]);
                if (rin && col >= 7 && col < 39) a3[col] = v;
                st[row][col] = v;
            }
        }
        for (int row = ty_; row < 40; row += 8){
            const float* a1 = xp + (Y0-4+row)*WV + X0-4;
            const float* a2 = pp + (Y0-4+row)*WV + X0-4;
            float* a3 = xo + (Y0-4+row)*WV + X0-4;
            bool rin = (row >= 4 && row < 36);
            for (int col = tx_; col < 40; col += 32){
                float v = first ? a1[col] : fmaf(al, a2[col], a1[col]);
                if (rin && col >= 4 && col < 36) a3[col] = v;
                sx[row][col] = v;
            }
        }
    } else if (inter){
        for (int row = ty_; row < 54; row += 8){
            const float* a1 = tp + (Y0-11+row)*WV + X0-11;
            const float* a2 = tq + (Y0-11+row)*WV + X0-11;
            float* a3 = to + (Y0-11+row)*WV + X0-11;
            bool rin = (row >= 11 && row < 43);
            for (int col = tx_; col < 54; col += 32){
                float v = first ? a1[col] : fmaf(al, a2[col], a1[col]);
                if (rin && col >= 11 && col < 43) a3[col] = v;
                st[row][col] = v;
            }
        }
        for (int row = ty_; row < 40; row += 8){
            const float* a1 = xp + (Y0-4+row)*WV + X0-4;
            const float* a2 = pp + (Y0-4+row)*WV + X0-4;
            float* a3 = xo + (Y0-4+row)*WV + X0-4;
            bool rin = (row >= 4 && row < 36);
            for (int col = tx_; col < 40; col += 32){
                float v = first ? a1[col] : fmaf(al, a2[col], a1[col]);
                if (rin && col >= 4 && col < 36) a3[col] = v;
                sx[row][col] = v;
            }
        }
    } else {
        for (int row = ty_; row < 54; row += 8){
            int gy = Y0 - 11 + row;
            bool iny = (unsigned)gy < HV;
            bool rin = (row >= 11 && row < 43);
            for (int col = tx_; col < 54; col += 32){
                int gx = X0 - 11 + col;
                float v = 0.f;
                if (iny && (unsigned)gx < WV){
                    int gi = gy*WV + gx;
                    v = first ? tp[gi] : fmaf(al, tq[gi], tp[gi]);
                    if (rin && col >= 11 && col < 43) to[gi] = v;
                }
                st[row][col] = v;
            }
        }
        for (int row = ty_; row < 40; row += 8){
            int gy = Y0 - 4 + row;
            bool iny = (unsigned)gy < HV;
            bool rin = (row >= 4 && row < 36);
            for (int col = tx_; col < 40; col += 32){
                int gx = X0 - 4 + col;
                float v = 0.f;
                if (iny && (unsigned)gx < WV){
                    int gi = gy*WV + gx;
                    v = first ? xp[gi] : fmaf(al, pp[gi], xp[gi]);
                    if (rin && col >= 4 && col < 36) xo[gi] = v;
                }
                sx[row][col] = v;
            }
        }
    }
    const float* kb = kern + b*225;
    for (int i = tid; i < 225; i += 256) sk[i] = kb[224 - i];
    for (int i = tid; i < 84; i += 256){ sSv[i] = g_Sv[stage][i]; sSo[i] = g_So40[stage][i]; }
    if (!fastD)
        for (int i = tid; i < 2116; i += 256) su[i] = 0.f;
    __syncthreads();

    if (!fastD){
        for (int n = 0; n < 6; n++){
            float w2 = g_dkw2[stage][n];
            if (w2 == 0.f) continue;
            int nt = g_dknt[stage][n];
            if (nt == 1){
                int dy = g_dkdy[stage][n][0], dx = g_dkdx[stage][n][0];
                float vv0 = g_dkv[stage][n][0];
                float wv2 = w2*vv0*vv0;
                if (inter){
                    for (int row = ty_; row < 46; row += 8)
                        for (int col = tx_; col < 46; col += 32)
                            su[row*46+col] = fmaf(wv2, st[row+4][col+4], su[row*46+col]);
                } else {
                    for (int row = ty_; row < 46; row += 8){
                        int gy = Y0 - 7 + row;
                        int iy = gy + 2 - dy;
                        bool okr = ((unsigned)gy < HV) && ((unsigned)iy < HV);
                        for (int col = tx_; col < 46; col += 32){
                            int gx = X0 - 7 + col;
                            int ix = gx + 2 - dx;
                            if (okr && (unsigned)gx < WV && (unsigned)ix < WV)
                                su[row*46+col] = fmaf(wv2, st[row+4][col+4], su[row*46+col]);
                        }
                    }
                }
            } else if (nt <= 4){
                T4 tf = t4_fwd_dk(stage, n, 54);
                for (int row = ty_; row < 50; row += 8){
                    int gy = Y0 - 9 + row;
                    bool iny = (unsigned)gy < HV;
                    for (int col = tx_; col < 50; col += 32){
                        int gx = X0 - 9 + col;
                        float a2 = 0.f;
                        if (inter || (iny && (unsigned)gx < WV)) a2 = w2*c4(&st[row][col], tf, 0.f);
                        sbuf[row*50+col] = a2;
                    }
                }
                __syncthreads();
                T4 ta = t4_adj_dk(stage, n, 50);
                for (int row = ty_; row < 46; row += 8){
                    int gy = Y0 - 7 + row;
                    bool iny = (unsigned)gy < HV;
                    for (int col = tx_; col < 46; col += 32){
                        int gx = X0 - 7 + col;
                        if (inter || (iny && (unsigned)gx < WV))
                            su[row*46+col] = c4(sbuf + row*50 + col, ta, su[row*46+col]);
                    }
                }
                __syncthreads();
            } else {
                for (int row = ty_; row < 50; row += 8){
                    int gy = Y0 - 9 + row;
                    bool iny = (unsigned)gy < HV;
                    for (int col = tx_; col < 50; col += 32){
                        int gx = X0 - 9 + col;
                        float a2 = 0.f;
                        if (inter || (iny && (unsigned)gx < WV)) a2 = w2*cg_fwd_dk(&st[row][col], stage, n, nt, 54, 0.f);
                        sbuf[row*50+col] = a2;
                    }
                }
                __syncthreads();
                for (int row = ty_; row < 46; row += 8){
                    int gy = Y0 - 7 + row;
                    bool iny = (unsigned)gy < HV;
                    for (int col = tx_; col < 46; col += 32){
                        int gx = X0 - 7 + col;
                        if (inter || (iny && (unsigned)gx < WV))
                            su[row*46+col] = cg_adj_dk(sbuf + row*50 + col, stage, n, nt, 50, su[row*46+col]);
                    }
                }
                __syncthreads();
            }
        }
        __syncthreads();
    }

    float acc[4] = {0,0,0,0};
    int rbase = ty_*4;
    if (fastD){
        for (int v = 0; v < 15; v++){
            float win[18];
            #pragma unroll
            for (int j = 0; j < 18; j++) win[j] = st[rbase+j][tx_+v];
            #pragma unroll
            for (int u = 0; u < 15; u++){
                float kv = sk[u*15+v];
                #pragma unroll
                for (int q = 0; q < 4; q++) acc[q] = fmaf(kv, win[u+q], acc[q]);
            }
        }
        float sc = g_scale1[stage];
        #pragma unroll
        for (int q = 0; q < 4; q++) acc[q] *= sc;
    } else {
        for (int v = 0; v < 15; v++){
            float win[18];
            #pragma unroll
            for (int j = 0; j < 18; j++) win[j] = su[(rbase+j)*46 + tx_+v];
            #pragma unroll
            for (int u = 0; u < 15; u++){
                float kv = sk[u*15+v];
                #pragma unroll
                for (int q = 0; q < 4; q++) acc[q] = fmaf(kv, win[u+q], acc[q]);
            }
        }
        __syncthreads();
    }

    // ---- regularizer term ----
    if (inter && p2){
        int nt4 = g_Snt4[stage];
        #pragma unroll
        for (int q = 0; q < 4; q++){
            const float* base = &sx[rbase+q+4][tx_+4];
            float a2 = acc[q];
            for (int t = 0; t < nt4; t += 4){
                a2 = fmaf(sSv[t],   base[sSo[t]],   a2);
                a2 = fmaf(sSv[t+1], base[sSo[t+1]], a2);
                a2 = fmaf(sSv[t+2], base[sSo[t+2]], a2);
                a2 = fmaf(sSv[t+3], base[sSo[t+3]], a2);
            }
            acc[q] = a2;
        }
        if (csrc){
            const float* cp = csrc + z*NPIX;
            #pragma unroll
            for (int q = 0; q < 4; q++)
                acc[q] -= cp[(Y0+rbase+q)*WV + X0 + tx_];
        }
    } else {
        for (int m = 0; m < 5; m++){
            float wm = rkw[stage*5+m];
            float pm = rpow[stage*5+m];
            float wp = wm*pm;
            int nt = g_rknt[stage][m];
            float* sph = pool + m*1296;
            const float* tg = tgt ? (tgt + (b*5+m)*CN + c*NPIX) : nullptr;
            float* vd = vdst + (b*5+m)*CN + c*NPIX;
            if (nt <= 4){
                T4 tf = t4_fwd_rk(stage, m, 40);
                for (int row = ty_; row < 36; row += 8){
                    int gy = Y0 - 2 + row;
                    bool iny = (unsigned)gy < HV;
                    bool rin = (row >= 2 && row < 34);
                    for (int col = tx_; col < 36; col += 32){
                        int gx = X0 - 2 + col;
                        float ph = 0.f;
                        if (iny && (unsigned)gx < WV){
                            float vv = c4(&sx[row][col], tf, 0.f);
                            int gi = gy*WV + gx;
                            if (tg) vv -= tg[gi];
                            if (p2){
                                ph = wp*sgnf(vv)*(fabsf(vv)+EPSF);
                            } else {
                                ph = wp*sgnf(vv)*powx(fabsf(vv)+EPSF, pm-1.f);
                                if (rin && col >= 2 && col < 34) vd[gi] = vv;
                            }
                        }
                        sph[row*36+col] = ph;
                    }
                }
            } else {
                for (int row = ty_; row < 36; row += 8){
                    int gy = Y0 - 2 + row;
                    bool iny = (unsigned)gy < HV;
                    bool rin = (row >= 2 && row < 34);
                    for (int col = tx_; col < 36; col += 32){
                        int gx = X0 - 2 + col;
                        float ph = 0.f;
                        if (iny && (unsigned)gx < WV){
                            float vv = cg_fwd_rk(&sx[row][col], stage, m, nt, 40, 0.f);
                            int gi = gy*WV + gx;
                            if (tg) vv -= tg[gi];
                            if (p2){
                                ph = wp*sgnf(vv)*(fabsf(vv)+EPSF);
                            } else {
                                ph = wp*sgnf(vv)*powx(fabsf(vv)+EPSF, pm-1.f);
                                if (rin && col >= 2 && col < 34) vd[gi] = vv;
                            }
                        }
                        sph[row*36+col] = ph;
                    }
                }
            }
        }
        __syncthreads();
        for (int m = 0; m < 5; m++){
            int nt = g_rknt[stage][m];
            const float* sph = pool + m*1296;
            if (nt <= 4){
                T4 ta = t4_adj_rk(stage, m, 36);
                #pragma unroll
                for (int q = 0; q < 4; q++)
                    acc[q] = c4(sph + (rbase+q)*36 + tx_, ta, acc[q]);
            } else {
                for (int q = 0; q < 4; q++)
                    acc[q] = cg_adj_rk(sph + (rbase+q)*36 + tx_, stage, m, nt, 36, acc[q]);
            }
        }
    }

    float* ro = rdst + z*NPIX;
    float ss = 0.f;
    #pragma unroll
    for (int q = 0; q < 4; q++){
        ro[(Y0+rbase+q)*WV + X0 + tx_] = -acc[q];
        ss = fmaf(acc[q], acc[q], ss);
    }
    __syncthreads();
    sh[tid] = ss; __syncthreads();
    for (int o = 128; o; o >>= 1){ if (tid < o) sh[tid] += sh[tid+o]; __syncthreads(); }
    if (tid == 0) g_partR[b*768 + c*256 + blockIdx.y*16 + blockIdx.x] = sh[0];
}

// ---------------- prior targets + c-term ----------------
__global__ void __launch_bounds__(256)
k_prior(const float* __restrict__ xsrc, float* __restrict__ dst, float* __restrict__ cdst,
        const float* __restrict__ thr,
        const float* __restrict__ rkw, const float* __restrict__ rpow, int stage)
{
    int z = blockIdx.z; int b = z/CV, c = z - b*CV;
    __shared__ float sxx[1600];
    __shared__ float pool[6480];
    int tx_ = threadIdx.x, ty_ = threadIdx.y;
    int tid = ty_*32 + tx_;
    int X0 = blockIdx.x*32, Y0 = blockIdx.y*32;
    const float* xp = xsrc + z*NPIX;
    for (int row = ty_; row < 40; row += 8){
        int gy = Y0-4+row;
        bool iny = (unsigned)gy < HV;
        for (int col = tx_; col < 40; col += 32){
            int gx = X0-4+col;
            sxx[row*40+col] = (iny && (unsigned)gx < WV) ? xp[gy*WV+gx] : 0.f;
        }
    }
    __syncthreads();
    int rbase = ty_*4;
    int gxo = X0 + tx_;
    for (int m = 0; m < 5; m++){
        int nt = g_rknt[stage][m];
        float th = thr[m];
        float wp = rkw[stage*5+m]*rpow[stage*5+m];
        float* sph = pool + m*1296;
        T4 tf = t4_fwd_rk(stage, m, 40);
        for (int row = ty_; row < 36; row += 8){
            int gy = Y0-2+row;
            bool iny = (unsigned)gy < HV;
            bool rin = (row >= 2 && row < 34);
            for (int col = tx_; col < 36; col += 32){
                int gx = X0-2+col;
                float shr = 0.f;
                if (iny && (unsigned)gx < WV){
                    float v;
                    if (nt <= 4) v = c4(&sxx[row*40+col], tf, 0.f);
                    else v = cg_fwd_rk(&sxx[row*40+col], stage, m, nt, 40, 0.f);
                    shr = sgnf(v)*fmaxf(fabsf(v)-th, 0.f);
                    if (rin && col >= 2 && col < 34)
                        dst[(b*5+m)*CN + c*NPIX + gy*WV + gx] = shr;
                }
                sph[row*36+col] = wp*shr;
            }
        }
    }
    __syncthreads();
    float cacc[4] = {0,0,0,0};
    for (int m = 0; m < 5; m++){
        int nt = g_rknt[stage][m];
        const float* sph = pool + m*1296;
        if (nt <= 4){
            T4 ta = t4_adj_rk(stage, m, 36);
            #pragma unroll
            for (int q = 0; q < 4; q++)
                cacc[q] = c4(sph + (rbase+q)*36 + tx_, ta, cacc[q]);
        } else {
            for (int q = 0; q < 4; q++)
                cacc[q] = cg_adj_rk(sph + (rbase+q)*36 + tx_, stage, m, nt, 36, cacc[q]);
        }
    }
    #pragma unroll
    for (int q = 0; q < 4; q++)
        cdst[z*NPIX + (Y0+rbase+q)*WV + gxo] = cacc[q];
}

// ---------------- bilateral grid (coalesced splat, folded x+alpha*p) ----------------
__global__ void __launch_bounds__(256)
k_splat(const float* __restrict__ x, const float* __restrict__ p,
        float* __restrict__ grid, int slot){
    int pcgy = blockIdx.x;
    int gy = pcgy & 63;
    int pc = pcgy >> 6;
    int b = pc / CV;
    int tid = threadIdx.x;
    __shared__ float srow[4096];
    __shared__ float sh[256], sh2[256], s_alpha;
    float al = alpha_reduce(b, slot, tid, sh, sh2, &s_alpha);
    const float* xp = x + pc*NPIX + (gy*8)*WV;
    const float* pq = p + pc*NPIX + (gy*8)*WV;
    for (int i = tid; i < 4096; i += 256) srow[i] = fmaf(al, pq[i], xp[i]);
    __syncthreads();
    if (tid < 64){
        int gx = tid;
        float bv[NBIN], bw[NBIN];
        #pragma unroll
        for (int z = 0; z < NBIN; z++){ bv[z] = 0.f; bw[z] = 0.f; }
        for (int dy = 0; dy < 8; dy++)
            for (int dx = 0; dx < 8; dx++){
                float I = srow[dy*512 + gx*8+dx];
                float Ic = fminf(fmaxf(I, 0.f), 1.f);
                int zi = (int)rintf(Ic * (float)(NBIN-1));
                zi = max(0, min(NBIN-1, zi));
                bv[zi] += Ic; bw[zi] += 1.f;
            }
        float* gp = grid + ((long)pcgy*64 + gx)*NBIN*2;
        #pragma unroll
        for (int z = 0; z < NBIN; z++){ gp[z*2] = bv[z]; gp[z*2+1] = bw[z]; }
    }
}

// fused separable grid filter: y-conv (11) -> x-conv (11) -> z-conv (5), one launch.
__global__ void __launch_bounds__(256)
k_bconv(const float* __restrict__ gin, float* __restrict__ gout,
        const float* __restrict__ fs, const float* __restrict__ fr)
{
    int blk = blockIdx.x;
    int txt = blk & 7; int tyt = (blk >> 3) & 7; int pc = blk >> 6;
    int Y0 = tyt*8, X0 = txt*8;
    __shared__ float sin[18*18*18];
    __shared__ float sy [8*18*18];
    __shared__ float sxz[8*8*18];
    __shared__ float sfs[11], sfr[5];
    int tid = threadIdx.x;
    const float* gp = gin + (long)pc*(GH*GW*NBIN*2);
    for (int i = tid; i < 18*18*18; i += 256){
        int k = i % 18; int rc = i / 18;
        int c0 = rc % 18, r0 = rc / 18;
        int gy = Y0 - 5 + r0, gx = X0 - 5 + c0;
        float v = 0.f;
        if ((unsigned)gy < GH && (unsigned)gx < GW)
            v = gp[(gy*GW + gx)*18 + k];
        sin[i] = v;
    }
    if (tid < 11) sfs[tid] = fs[tid];
    if (tid < 5)  sfr[tid] = fr[tid];
    __syncthreads();
    for (int i = tid; i < 8*18*18; i += 256){
        int k = i % 18; int rc = i / 18;
        int c0 = rc % 18, r0 = rc / 18;
        const float* bp = sin + (r0*18 + c0)*18 + k;
        float s = 0.f;
        #pragma unroll
        for (int t = 0; t < 11; t++) s = fmaf(sfs[t], bp[t*324], s);
        sy[i] = s;
    }
    __syncthreads();
    for (int i = tid; i < 8*8*18; i += 256){
        int k = i % 18; int rc = i / 18;
        int c0 = rc % 8, r0 = rc / 8;
        const float* bp = sy + (r0*18 + c0)*18 + k;
        float s = 0.f;
        #pragma unroll
        for (int t = 0; t < 11; t++) s = fmaf(sfs[t], bp[t*18], s);
        sxz[i] = s;
    }
    __syncthreads();
    float* go = gout + (long)pc*(GH*GW*NBIN*2);
    for (int i = tid; i < 8*8*18; i += 256){
        int k = i % 18; int rc = i / 18;
        int ch = k & 1; int zz = k >> 1;
        const float* bp = sxz + rc*18 + ch;
        float s = 0.f;
        #pragma unroll
        for (int t = 0; t < 5; t++){
            int cc = zz + t - 2;
            if ((unsigned)cc < NBIN) s = fmaf(sfr[t], bp[cc*2], s);
        }
        int r0 = rc / 8, c0 = rc % 8;
        go[((Y0+r0)*GW + X0+c0)*18 + k] = s;
    }
}

// slice with folded x+alpha*p input; writes result to xout
__global__ void k_slice(const float* __restrict__ xsrc, const float* __restrict__ psrc,
                        float* __restrict__ xout, const float* __restrict__ grid, int slot){
    int i = blockIdx.x*blockDim.x + threadIdx.x;
    int tid = threadIdx.x;
    int pc = i / NPIX;
    int b = pc / CV;
    __shared__ float sh[256], sh2[256], s_alpha;
    float al = alpha_reduce(b, slot, tid, sh, sh2, &s_alpha);
    if (i >= BCN) return;
    int pix = i - pc*NPIX;
    int y = pix / WV, xx = pix - y*WV;
    float I = fmaf(al, psrc[i], xsrc[i]);
    float Ic = fminf(fmaxf(I, 0.f), 1.f);
    float yf = (float)y * 0.125f;
    float xf = (float)xx * 0.125f;
    float zf = Ic * (float)(NBIN-1);
    int y0 = max(0, min(GH-1, (int)floorf(yf)));  int y1 = min(y0+1, GH-1);
    float wy = fminf(fmaxf(yf - (float)y0, 0.f), 1.f);
    int x0 = max(0, min(GW-1, (int)floorf(xf)));  int x1 = min(x0+1, GW-1);
    float wx = fminf(fmaxf(xf - (float)x0, 0.f), 1.f);
    int z0 = max(0, min(NBIN-1, (int)floorf(zf))); int z1 = min(z0+1, NBIN-1);
    float wz = fminf(fmaxf(zf - (float)z0, 0.f), 1.f);
    const float* gp = grid + (long)pc*GH*GW*NBIN*2;
    float a0 = 0.f, a1 = 0.f;
    int ys[2]   = {y0, y1};  float wys[2] = {1.f-wy, wy};
    int xs[2]   = {x0, x1};  float wxs[2] = {1.f-wx, wx};
    int zs[2]   = {z0, z1};  float wzs[2] = {1.f-wz, wz};
    for (int a = 0; a < 2; a++)
        for (int bb = 0; bb < 2; bb++)
            for (int cc = 0; cc < 2; cc++){
                float w = wys[a]*wxs[bb]*wzs[cc];
                int idx = (((ys[a]*GW) + xs[bb])*NBIN + zs[cc])*2;
                a0 = fmaf(w, gp[idx], a0);
                a1 = fmaf(w, gp[idx+1], a1);
            }
    xout[i] = a0 / (a1 + 1e-8f);
}

// ---------------- host orchestration ----------------
extern "C" void kernel_launch(void* const* d_in, const int* in_sizes, int n_in,
                              void* d_out, int out_size)
{
    const float* blurred = (const float*)d_in[0];
    const float* kern    = (const float*)d_in[1];
    const float* dks     = (const float*)d_in[2];
    const float* dkw     = (const float*)d_in[3];
    const float* rks     = (const float*)d_in[4];
    const float* rkw     = (const float*)d_in[5];
    const float* rpow    = (const float*)d_in[6];
    const float* fs      = (const float*)d_in[7];
    const float* fr      = (const float*)d_in[8];
    const float* thr     = (const float*)d_in[9];
    const int NCG = 5;

    float *px, *px2, *pr, *pp, *pp2, *pt, *pt2, *ptp, *pv, *ptg, *pgA, *pgB;
    cudaGetSymbolAddress((void**)&px,  g_x);
    cudaGetSymbolAddress((void**)&px2, g_x2);
    cudaGetSymbolAddress((void**)&pr,  g_r);
    cudaGetSymbolAddress((void**)&pp,  g_p);
    cudaGetSymbolAddress((void**)&pp2, g_p2);
    cudaGetSymbolAddress((void**)&pt,  g_t);
    cudaGetSymbolAddress((void**)&pt2, g_t2);
    cudaGetSymbolAddress((void**)&ptp, g_tp);
    cudaGetSymbolAddress((void**)&pv,  g_v);
    cudaGetSymbolAddress((void**)&ptg, g_tgt);
    cudaGetSymbolAddress((void**)&pgA, g_gridA);
    cudaGetSymbolAddress((void**)&pgB, g_gridB);

    dim3 cb(32, 8);
    dim3 cg15(16, 8, BV*CV);
    dim3 cg32(16, 16, BV*CV);
    int EW = (BCN + 255)/256;

    k_prep<<<1,32>>>(dks, dkw, rks, rkw, rpow);

    const float* s0x = nullptr; const float* s0p = nullptr; int s0slot = 0;
    auto cgrun = [&](int stage, const float* tgt, const float* cbuf,
                     const float* xin, float* xfinal){
        float* tcur = pt;   float* tnxt = pt2;
        float* pcur = pp;   float* pnxt = pp2;
        k_conv15<<<cg15,cb>>>(xin, tcur, kern, blurred);
        float* xcur = (xin == px) ? px2 : px;
        k_gradfull<<<cg32,cb>>>(xin, pcur, tcur, ptp, xcur, tnxt, tgt, cbuf, pr, pv,
                                kern, rkw, rpow, stage, 0, 1);
        { float* q = tcur; tcur = tnxt; tnxt = q; }
        for (int it = 0; it < NCG; it++){
            int rs = it & 1, ws = rs ^ 1;
            k_pstep<<<cg15,cb>>>(pcur, pnxt, ptp, pr, kern, rkw, rpow, stage, it == 0, rs);
            if (it == NCG-1){
                if (xfinal){
                    k_axpy_final<<<dim3(256,BV),256>>>(xcur, pnxt, xfinal, ws);
                } else {
                    s0x = xcur; s0p = pnxt; s0slot = ws;
                }
            } else {
                float* xd = (xcur == px) ? px2 : px;
                k_gradfull<<<cg32,cb>>>(xcur, pnxt, tcur, ptp, xd, tnxt, tgt, cbuf, pr, pv,
                                        kern, rkw, rpow, stage, ws, 0);
                xcur = xd;
                { float* q = tcur; tcur = tnxt; tnxt = q; }
            }
            { float* q = pcur; pcur = pnxt; pnxt = q; }
        }
    };

    // Stage 0 (targets = 0, c = 0); final axpy deferred into splat/slice
    cgrun(0, nullptr, nullptr, blurred, nullptr);

    float* xbi = (s0x == px) ? px2 : px;
    k_splat<<<BV*CV*GH, 256>>>(s0x, s0p, pgA, s0slot);
    k_bconv<<<BV*CV*64, 256>>>(pgA, pgB, fs, fr);
    k_slice<<<EW,256>>>(s0x, s0p, xbi, pgB, s0slot);

    k_prior<<<cg32,cb>>>(xbi, ptg, pv, thr, rkw, rpow, 1);
    cgrun(1, ptg, pv, xbi, (float*)d_out);
}

// round 16
// speedup vs baseline: 1.0729x; 1.0015x over previous
#include <cuda_runtime.h>

#define BV 2
#define CV 3
#define HV 512
#define WV 512
#define NPIX (HV*WV)
#define CN (CV*NPIX)
#define BCN (BV*CN)
#define GH 64
#define GW 64
#define NBIN 9
#define NGRID (BV*CV*GH*GW*NBIN*2)
#define EPSF 1e-8f
#define CG_TOL 1e-4f

// ---------------- scratch (device globals; no allocation) ----------------
__device__ float g_x[BCN], g_x2[BCN];
__device__ float g_r[BCN];
__device__ float g_p[BCN], g_p2[BCN];
__device__ float g_t[BCN], g_t2[BCN];
__device__ float g_tp[BCN];
__device__ float g_v[BV*5*CN];        // reused: [0..BCN) holds c-term for stage 1
__device__ float g_tgt[BV*5*CN];
__device__ float g_gridA[NGRID], g_gridB[NGRID];
__device__ float g_partN[BV*192];
__device__ float g_partDf[BV*192];
__device__ float g_partR[BV*768];
__device__ float g_r0[BV];
__device__ float g_rnS[2][BV];
__device__ int   g_doneS[2][BV];

// sparse tap metadata, zero-padded (exact: fmaf(0,x,a)==a for finite x)
__device__ int   g_dknt[2][6];
__device__ int   g_dkdy[2][6][25];
__device__ int   g_dkdx[2][6][25];
__device__ float g_dkv [2][6][25];
__device__ float g_dkw2[2][6];
__device__ int   g_rknt[2][5];
__device__ int   g_rkdy[2][5][25];
__device__ int   g_rkdx[2][5][25];
__device__ float g_rkv [2][5][25];
__device__ int   g_fastDk[2];
__device__ float g_scale1[2];
__device__ int   g_allp2[2];
__device__ int   g_fusedDen[2];
__device__ int   g_Snt4[2];
__device__ float g_Sv[2][84];
__device__ int   g_So40[2][84];

__device__ __forceinline__ float powx(float a, float e){
    if (e == 0.0f) return 1.0f;
    if (e == 1.0f) return a;
    return powf(a, e);
}
__device__ __forceinline__ float sgnf(float v){
    return (v > 0.f) ? 1.f : ((v < 0.f) ? -1.f : 0.f);
}

struct T4 { float v0,v1,v2,v3; int o0,o1,o2,o3; };
__device__ __forceinline__ T4 t4_fwd_rk(int s,int m,int st){
    T4 t;
    t.v0=g_rkv[s][m][0]; t.v1=g_rkv[s][m][1]; t.v2=g_rkv[s][m][2]; t.v3=g_rkv[s][m][3];
    t.o0=g_rkdy[s][m][0]*st+g_rkdx[s][m][0]; t.o1=g_rkdy[s][m][1]*st+g_rkdx[s][m][1];
    t.o2=g_rkdy[s][m][2]*st+g_rkdx[s][m][2]; t.o3=g_rkdy[s][m][3]*st+g_rkdx[s][m][3];
    return t;
}
__device__ __forceinline__ T4 t4_adj_rk(int s,int m,int st){
    T4 t;
    t.v0=g_rkv[s][m][0]; t.v1=g_rkv[s][m][1]; t.v2=g_rkv[s][m][2]; t.v3=g_rkv[s][m][3];
    t.o0=(4-g_rkdy[s][m][0])*st+(4-g_rkdx[s][m][0]); t.o1=(4-g_rkdy[s][m][1])*st+(4-g_rkdx[s][m][1]);
    t.o2=(4-g_rkdy[s][m][2])*st+(4-g_rkdx[s][m][2]); t.o3=(4-g_rkdy[s][m][3])*st+(4-g_rkdx[s][m][3]);
    return t;
}
__device__ __forceinline__ T4 t4_fwd_dk(int s,int n,int st){
    T4 t;
    t.v0=g_dkv[s][n][0]; t.v1=g_dkv[s][n][1]; t.v2=g_dkv[s][n][2]; t.v3=g_dkv[s][n][3];
    t.o0=g_dkdy[s][n][0]*st+g_dkdx[s][n][0]; t.o1=g_dkdy[s][n][1]*st+g_dkdx[s][n][1];
    t.o2=g_dkdy[s][n][2]*st+g_dkdx[s][n][2]; t.o3=g_dkdy[s][n][3]*st+g_dkdx[s][n][3];
    return t;
}
__device__ __forceinline__ T4 t4_adj_dk(int s,int n,int st){
    T4 t;
    t.v0=g_dkv[s][n][0]; t.v1=g_dkv[s][n][1]; t.v2=g_dkv[s][n][2]; t.v3=g_dkv[s][n][3];
    t.o0=(4-g_dkdy[s][n][0])*st+(4-g_dkdx[s][n][0]); t.o1=(4-g_dkdy[s][n][1])*st+(4-g_dkdx[s][n][1]);
    t.o2=(4-g_dkdy[s][n][2])*st+(4-g_dkdx[s][n][2]); t.o3=(4-g_dkdy[s][n][3])*st+(4-g_dkdx[s][n][3]);
    return t;
}
__device__ __forceinline__ float c4(const float* p, const T4& t, float a){
    a = fmaf(t.v0, p[t.o0], a);
    a = fmaf(t.v1, p[t.o1], a);
    a = fmaf(t.v2, p[t.o2], a);
    a = fmaf(t.v3, p[t.o3], a);
    return a;
}
__device__ __forceinline__ float cg_fwd_dk(const float* p,int s,int n,int nt,int st,float a){
    for (int t = 0; t < nt; t++) a = fmaf(g_dkv[s][n][t], p[g_dkdy[s][n][t]*st+g_dkdx[s][n][t]], a);
    return a;
}
__device__ __forceinline__ float cg_adj_dk(const float* p,int s,int n,int nt,int st,float a){
    for (int t = 0; t < nt; t++) a = fmaf(g_dkv[s][n][t], p[(4-g_dkdy[s][n][t])*st+(4-g_dkdx[s][n][t])], a);
    return a;
}
__device__ __forceinline__ float cg_fwd_rk(const float* p,int s,int m,int nt,int st,float a){
    for (int t = 0; t < nt; t++) a = fmaf(g_rkv[s][m][t], p[g_rkdy[s][m][t]*st+g_rkdx[s][m][t]], a);
    return a;
}
__device__ __forceinline__ float cg_adj_rk(const float* p,int s,int m,int nt,int st,float a){
    for (int t = 0; t < nt; t++) a = fmaf(g_rkv[s][m][t], p[(4-g_rkdy[s][m][t])*st+(4-g_rkdx[s][m][t])], a);
    return a;
}
// deterministic alpha reduction over 192-slot partials (identical everywhere)
__device__ __forceinline__ float alpha_reduce(int b, int slot, int tid,
                                              float* sh, float* sh2, float* s_alpha)
{
    float sn = 0.f, sd = 0.f;
    if (tid < 64){
        sn = g_partN [b*192+tid] + g_partN [b*192+64+tid] + g_partN [b*192+128+tid];
        sd = g_partDf[b*192+tid] + g_partDf[b*192+64+tid] + g_partDf[b*192+128+tid];
    }
    sh[tid] = sn; sh2[tid] = sd; __syncthreads();
    for (int o = 128; o; o >>= 1){
        if (tid < o){ sh[tid] += sh[tid+o]; sh2[tid] += sh2[tid+o]; }
        __syncthreads();
    }
    if (tid == 0){
        int dn = g_doneS[slot][b];
        *s_alpha = dn ? 0.f : sh[0]/(sh2[0] + 1e-12f);
    }
    __syncthreads();
    return *s_alpha;
}

// ---------------- prep ----------------
__global__ void k_prep(const float* __restrict__ dks, const float* __restrict__ dkw,
                       const float* __restrict__ rks, const float* __restrict__ rkw,
                       const float* __restrict__ rpow)
{
    if (threadIdx.x != 0 || blockIdx.x != 0) return;
    for (int s = 0; s < 2; s++){
        int fast = 1, center1 = 1; float sc1 = 0.f;
        for (int n = 0; n < 6; n++){
            float w2 = 2.f*dkw[s*6+n];
            g_dkw2[s][n] = w2;
            int cnt = 0;
            for (int j = 0; j < 25; j++){
                float v = dks[(s*6+n)*25 + j];
                if (v != 0.f){
                    g_dkdy[s][n][cnt] = j/5; g_dkdx[s][n][cnt] = j%5;
                    g_dkv [s][n][cnt] = v; cnt++;
                }
            }
            g_dknt[s][n] = cnt;
            for (int j = cnt; j < 25; j++){ g_dkdy[s][n][j]=0; g_dkdx[s][n][j]=0; g_dkv[s][n][j]=0.f; }
            if (w2 != 0.f){
                if (cnt == 1){
                    sc1 += w2*g_dkv[s][n][0]*g_dkv[s][n][0];
                    if (g_dkdy[s][n][0] != 2 || g_dkdx[s][n][0] != 2) center1 = 0;
                } else { fast = 0; center1 = 0; }
            }
        }
        g_fastDk[s] = fast;
        g_scale1[s] = sc1;
        int p2 = 1;
        for (int m = 0; m < 5; m++){
            if (rpow[s*5+m] != 2.0f) p2 = 0;
            int cnt = 0;
            for (int j = 0; j < 25; j++){
                float v = rks[(s*5+m)*25 + j];
                if (v != 0.f){
                    g_rkdy[s][m][cnt] = j/5; g_rkdx[s][m][cnt] = j%5;
                    g_rkv [s][m][cnt] = v; cnt++;
                }
            }
            g_rknt[s][m] = cnt;
            for (int j = cnt; j < 25; j++){ g_rkdy[s][m][j]=0; g_rkdx[s][m][j]=0; g_rkv[s][m][j]=0.f; }
        }
        g_allp2[s] = p2;
        g_fusedDen[s] = p2 && center1;

        float Sbuf[81];
        for (int j = 0; j < 81; j++) Sbuf[j] = 0.f;
        for (int m = 0; m < 5; m++){
            float wp = rkw[s*5+m]*rpow[s*5+m];
            int nt = g_rknt[s][m];
            for (int t1 = 0; t1 < nt; t1++)
                for (int t2 = 0; t2 < nt; t2++){
                    int ody = g_rkdy[s][m][t1] - g_rkdy[s][m][t2];
                    int odx = g_rkdx[s][m][t1] - g_rkdx[s][m][t2];
                    Sbuf[(ody+4)*9 + (odx+4)] += wp*g_rkv[s][m][t1]*g_rkv[s][m][t2];
                }
        }
        int cnt = 0;
        for (int j = 0; j < 81; j++){
            if (Sbuf[j] != 0.f){
                g_Sv[s][cnt] = Sbuf[j];
                g_So40[s][cnt] = (j/9 - 4)*40 + (j%9 - 4);
                cnt++;
            }
        }
        while (cnt & 3){ g_Sv[s][cnt] = 0.f; g_So40[s][cnt] = 0; cnt++; }
        g_Snt4[s] = cnt;
    }
}

// ---------------- plain 15x15 conv - sub (CG init only), 32x128 tile, RY=16 ---------
__global__ void __launch_bounds__(256)
k_conv15(const float* __restrict__ src, float* __restrict__ dst,
         const float* __restrict__ kern, const float* __restrict__ sub)
{
    int z = blockIdx.z; int b = z / CV;
    __shared__ float tile[142][46];
    __shared__ float sk[225];
    const float* sp = src + z*NPIX;
    int X0 = blockIdx.x*32, Y0 = blockIdx.y*128;
    int x0 = X0 - 7, y0 = Y0 - 7;
    int tx_ = threadIdx.x, ty_ = threadIdx.y;
    int tid = ty_*32 + tx_;
    bool inter = (Y0 >= 7) && (Y0 + 135 <= HV) && (X0 >= 7) && (X0 + 39 <= WV);
    if (inter){
        for (int row = ty_; row < 142; row += 8){
            const float* rp = sp + (y0+row)*WV + x0;
            for (int col = tx_; col < 46; col += 32) tile[row][col] = rp[col];
        }
    } else {
        for (int row = ty_; row < 142; row += 8){
            int gy = y0 + row;
            bool iny = (unsigned)gy < HV;
            for (int col = tx_; col < 46; col += 32){
                int gx = x0 + col;
                tile[row][col] = (iny && (unsigned)gx < WV) ? sp[gy*WV+gx] : 0.f;
            }
        }
    }
    const float* kb = kern + b*225;
    for (int i = tid; i < 225; i += 256) sk[i] = kb[i];
    __syncthreads();
    float acc[16];
    #pragma unroll
    for (int q = 0; q < 16; q++) acc[q] = 0.f;
    int rbase = ty_*16;
    for (int v = 0; v < 15; v++){
        float win[30];
        #pragma unroll
        for (int j = 0; j < 30; j++) win[j] = tile[rbase+j][tx_+v];
        #pragma unroll
        for (int u = 0; u < 15; u++){
            float kv = sk[u*15+v];
            #pragma unroll
            for (int q = 0; q < 16; q++) acc[q] = fmaf(kv, win[u+q], acc[q]);
        }
    }
    int gx = X0 + tx_;
    int gyb = Y0 + rbase;
    #pragma unroll
    for (int q = 0; q < 16; q++){
        int oi = z*NPIX + (gyb+q)*WV + gx;
        float o = acc[q];
        if (sub) o -= sub[oi];
        dst[oi] = o;
    }
}

// ---- fused: beta/done + p update + Kp conv + num + den, 32x128 tile, RY=16 ---------
__global__ void __launch_bounds__(256)
k_pstep(const float* __restrict__ pold, float* __restrict__ pnew,
        float* __restrict__ kp, const float* __restrict__ rsrc,
        const float* __restrict__ kern,
        const float* __restrict__ rkw, const float* __restrict__ rpow,
        int stage, int first, int slot)
{
    int z = blockIdx.z; int b = z/CV, c = z - b*CV;
    int tx_ = threadIdx.x, ty_ = threadIdx.y;
    int tid = ty_*32 + tx_;
    __shared__ float pn[142][46];
    __shared__ float sk[225];
    __shared__ float sh[256];
    __shared__ float sh2[256];
    __shared__ float s_beta;
    __shared__ int s_freeze;

    float a = g_partR[b*768+tid] + g_partR[b*768+256+tid] + g_partR[b*768+512+tid];
    sh[tid] = a; __syncthreads();
    for (int o = 128; o; o >>= 1){ if (tid < o) sh[tid] += sh[tid+o]; __syncthreads(); }
    if (tid == 0){
        float nrn = sh[0];
        int done_prev = first ? 0 : g_doneS[slot][b];
        float rn_prev = first ? 1.f : g_rnS[slot][b];
        float r0 = first ? nrn : g_r0[b];
        int conv_now = (!first) && (nrn < CG_TOL*r0);
        s_beta = first ? 0.f : nrn/(rn_prev + 1e-20f);
        s_freeze = first ? 0 : (done_prev | conv_now);
        if (blockIdx.x == 0 && blockIdx.y == 0 && c == 0){
            g_doneS[slot^1][b] = done_prev | conv_now;
            g_rnS[slot^1][b] = done_prev ? rn_prev : nrn;
            if (first) g_r0[b] = nrn;
        }
    }
    __syncthreads();
    int X0 = blockIdx.x*32, Y0 = blockIdx.y*128;
    if (s_freeze){
        const float* pop = pold + z*NPIX;
        float* pno = pnew + z*NPIX;
        for (int row = ty_; row < 128; row += 8){
            int gi = (Y0+row)*WV + X0 + tx_;
            pno[gi] = pop[gi];
        }
        return;
    }
    float beta = s_beta;
    const float* rp = rsrc + z*NPIX;
    const float* pop = pold + z*NPIX;
    float* pno = pnew + z*NPIX;
    int x0 = X0 - 7, y0 = Y0 - 7;
    bool inter = (Y0 >= 7) && (Y0 + 135 <= HV) && (X0 >= 7) && (X0 + 39 <= WV);
    float s = 0.f;
    if (inter){
        for (int row = ty_; row < 142; row += 8){
            const float* rr = rp + (y0+row)*WV + x0;
            const float* pr2 = pop + (y0+row)*WV + x0;
            float* pw = pno + (y0+row)*WV + x0;
            bool rin = (row >= 7 && row < 135);
            for (int col = tx_; col < 46; col += 32){
                float rv = rr[col];
                float v = first ? rv : fmaf(beta, pr2[col], rv);
                if (rin && col >= 7 && col < 39){
                    pw[col] = v;
                    s = fmaf(rv, v, s);
                }
                pn[row][col] = v;
            }
        }
    } else {
        for (int row = ty_; row < 142; row += 8){
            int gy = y0 + row;
            bool iny = (unsigned)gy < HV;
            bool rin = (row >= 7 && row < 135);
            for (int col = tx_; col < 46; col += 32){
                int gx = x0 + col;
                float v = 0.f;
                if (iny && (unsigned)gx < WV){
                    int gi = gy*WV + gx;
                    float rv = rp[gi];
                    v = first ? rv : fmaf(beta, pop[gi], rv);
                    if (rin && col >= 7 && col < 39){
                        pno[gi] = v;
                        s = fmaf(rv, v, s);
                    }
                }
                pn[row][col] = v;
            }
        }
    }
    const float* kb = kern + b*225;
    for (int i = tid; i < 225; i += 256) sk[i] = kb[i];
    __syncthreads();
    float acc[16];
    #pragma unroll
    for (int q = 0; q < 16; q++) acc[q] = 0.f;
    int rbase = ty_*16;
    for (int v = 0; v < 15; v++){
        float win[30];
        #pragma unroll
        for (int j = 0; j < 30; j++) win[j] = pn[rbase+j][tx_+v];
        #pragma unroll
        for (int u = 0; u < 15; u++){
            float kv = sk[u*15+v];
            #pragma unroll
            for (int q = 0; q < 16; q++) acc[q] = fmaf(kv, win[u+q], acc[q]);
        }
    }
    float* ko = kp + z*NPIX;
    #pragma unroll
    for (int q = 0; q < 16; q++)
        ko[(Y0+rbase+q)*WV + X0 + tx_] = acc[q];

    // fused denominator (exact: all rpow==2 and data filters are center deltas)
    float sden = 0.f;
    {
        float sc1 = g_scale1[stage];
        #pragma unroll
        for (int q = 0; q < 16; q++) sden = fmaf(sc1*acc[q], acc[q], sden);
        for (int m = 0; m < 5; m++){
            int nt = g_rknt[stage][m];
            float pmv = rpow[stage*5+m];
            float wc = rkw[stage*5+m]*pmv*(pmv-1.f);
            if (nt <= 4){
                T4 tf = t4_fwd_rk(stage, m, 46);
                #pragma unroll
                for (int q = 0; q < 16; q++){
                    float rv = c4(&pn[rbase+q+5][tx_+5], tf, 0.f);
                    sden = fmaf(wc*rv, rv, sden);
                }
            } else {
                for (int q = 0; q < 16; q++){
                    float rv = cg_fwd_rk(&pn[rbase+q+5][tx_+5], stage, m, nt, 46, 0.f);
                    sden = fmaf(wc*rv, rv, sden);
                }
            }
        }
    }
    __syncthreads();
    sh[tid] = s; sh2[tid] = sden; __syncthreads();
    for (int o = 128; o; o >>= 1){
        if (tid < o){ sh[tid] += sh[tid+o]; sh2[tid] += sh2[tid+o]; }
        __syncthreads();
    }
    if (tid == 0){
        g_partN [b*192 + c*64 + blockIdx.y*16 + blockIdx.x] = sh[0];
        g_partDf[b*192 + c*64 + blockIdx.y*16 + blockIdx.x] = sh2[0];
    }
}

// ---------------- final-iteration axpy (stage 1 only) ----------------
__global__ void k_axpy_final(const float* __restrict__ xsrc, const float* __restrict__ psrc,
                             float* __restrict__ xdst, int slot)
{
    int b = blockIdx.y;
    int tid = threadIdx.x;
    __shared__ float sh[256], sh2[256], s_alpha;
    float al = alpha_reduce(b, slot, tid, sh, sh2, &s_alpha);
    const float* xp = xsrc + b*CN;
    const float* pp = psrc + b*CN;
    float* xo = xdst + b*CN;
    for (int i = blockIdx.x*256 + tid; i < CN; i += 65536)
        xo[i] = fmaf(al, pp[i], xp[i]);
}

// ---------------- fused gradient + x/t update + r-norm partial ----------------
__global__ void __launch_bounds__(256,5)
k_gradfull(const float* __restrict__ xsrc, const float* __restrict__ psrc,
           const float* __restrict__ tsrc, const float* __restrict__ tpsrc,
           float* __restrict__ xdst, float* __restrict__ tdst,
           const float* __restrict__ tgt, const float* __restrict__ csrc,
           float* __restrict__ rdst, float* __restrict__ vdst,
           const float* __restrict__ kern,
           const float* __restrict__ rkw, const float* __restrict__ rpow,
           int stage, int slot, int first)
{
    int z = blockIdx.z; int b = z/CV, c = z - b*CV;
    int tx_ = threadIdx.x, ty_ = threadIdx.y;
    int tid = ty_*32 + tx_;
    int X0 = blockIdx.x*32, Y0 = blockIdx.y*32;

    int dn = first ? 0 : g_doneS[slot][b];
    if (dn){
        const float* xp = xsrc + z*NPIX;
        const float* tp = tsrc + z*NPIX;
        float* xo = xdst + z*NPIX;
        float* to = tdst + z*NPIX;
        for (int row = ty_; row < 32; row += 8){
            int gi = (Y0+row)*WV + X0 + tx_;
            xo[gi] = xp[gi];
            to[gi] = tp[gi];
        }
        return;
    }

    __shared__ float st[54][54];
    __shared__ float sx[40][40];
    __shared__ float pool[6480];
    __shared__ float sk[225];
    __shared__ float sSv[84];
    __shared__ int   sSo[84];
    __shared__ float sh[256];
    __shared__ float sh2[256];
    __shared__ float s_alpha;

    if (first){
        if (tid == 0) s_alpha = 0.f;
        __syncthreads();
    } else {
        alpha_reduce(b, slot, tid, sh, sh2, &s_alpha);
    }
    float al = s_alpha;

    const float* xp = xsrc + z*NPIX;
    const float* pp = psrc + z*NPIX;
    const float* tp = tsrc + z*NPIX;
    const float* tq = tpsrc + z*NPIX;
    float* xo = xdst + z*NPIX;
    float* to = tdst + z*NPIX;

    bool inter = (Y0 >= 11) && (Y0 + 43 <= HV) && (X0 >= 11) && (X0 + 43 <= WV);
    bool fastD = inter && (g_fastDk[stage] != 0);
    int p2 = g_allp2[stage];
    float* su = pool;
    float* sbuf = pool + 2116;

    if (fastD){
        for (int row = ty_; row < 46; row += 8){
            const float* a1 = tp + (Y0-7+row)*WV + X0-7;
            const float* a2 = tq + (Y0-7+row)*WV + X0-7;
            float* a3 = to + (Y0-7+row)*WV + X0-7;
            bool rin = (row >= 7 && row < 39);
            for (int col = tx_; col < 46; col += 32){
                float v = first ? a1[col] : fmaf(al, a2[col], a1[col]);
                if (rin && col >= 7 && col < 39) a3[col] = v;
                st[row][col] = v;
            }
        }
        for (int row = ty_; row < 40; row += 8){
            const float* a1 = xp + (Y0-4+row)*WV + X0-4;
            const float* a2 = pp + (Y0-4+row)*WV + X0-4;
            float* a3 = xo + (Y0-4+row)*WV + X0-4;
            bool rin = (row >= 4 && row < 36);
            for (int col = tx_; col < 40; col += 32){
                float v = first ? a1[col] : fmaf(al, a2[col], a1[col]);
                if (rin && col >= 4 && col < 36) a3[col] = v;
                sx[row][col] = v;
            }
        }
    } else if (inter){
        for (int row = ty_; row < 54; row += 8){
            const float* a1 = tp + (Y0-11+row)*WV + X0-11;
            const float* a2 = tq + (Y0-11+row)*WV + X0-11;
            float* a3 = to + (Y0-11+row)*WV + X0-11;
            bool rin = (row >= 11 && row < 43);
            for (int col = tx_; col < 54; col += 32){
                float v = first ? a1[col] : fmaf(al, a2[col], a1[col]);
                if (rin && col >= 11 && col < 43) a3[col] = v;
                st[row][col] = v;
            }
        }
        for (int row = ty_; row < 40; row += 8){
            const float* a1 = xp + (Y0-4+row)*WV + X0-4;
            const float* a2 = pp + (Y0-4+row)*WV + X0-4;
            float* a3 = xo + (Y0-4+row)*WV + X0-4;
            bool rin = (row >= 4 && row < 36);
            for (int col = tx_; col < 40; col += 32){
                float v = first ? a1[col] : fmaf(al, a2[col], a1[col]);
                if (rin && col >= 4 && col < 36) a3[col] = v;
                sx[row][col] = v;
            }
        }
    } else {
        for (int row = ty_; row < 54; row += 8){
            int gy = Y0 - 11 + row;
            bool iny = (unsigned)gy < HV;
            bool rin = (row >= 11 && row < 43);
            for (int col = tx_; col < 54; col += 32){
                int gx = X0 - 11 + col;
                float v = 0.f;
                if (iny && (unsigned)gx < WV){
                    int gi = gy*WV + gx;
                    v = first ? tp[gi] : fmaf(al, tq[gi], tp[gi]);
                    if (rin && col >= 11 && col < 43) to[gi] = v;
                }
                st[row][col] = v;
            }
        }
        for (int row = ty_; row < 40; row += 8){
            int gy = Y0 - 4 + row;
            bool iny = (unsigned)gy < HV;
            bool rin = (row >= 4 && row < 36);
            for (int col = tx_; col < 40; col += 32){
                int gx = X0 - 4 + col;
                float v = 0.f;
                if (iny && (unsigned)gx < WV){
                    int gi = gy*WV + gx;
                    v = first ? xp[gi] : fmaf(al, pp[gi], xp[gi]);
                    if (rin && col >= 4 && col < 36) xo[gi] = v;
                }
                sx[row][col] = v;
            }
        }
    }
    const float* kb = kern + b*225;
    for (int i = tid; i < 225; i += 256) sk[i] = kb[224 - i];
    for (int i = tid; i < 84; i += 256){ sSv[i] = g_Sv[stage][i]; sSo[i] = g_So40[stage][i]; }
    if (!fastD)
        for (int i = tid; i < 2116; i += 256) su[i] = 0.f;
    __syncthreads();

    if (!fastD){
        for (int n = 0; n < 6; n++){
            float w2 = g_dkw2[stage][n];
            if (w2 == 0.f) continue;
            int nt = g_dknt[stage][n];
            if (nt == 1){
                int dy = g_dkdy[stage][n][0], dx = g_dkdx[stage][n][0];
                float vv0 = g_dkv[stage][n][0];
                float wv2 = w2*vv0*vv0;
                if (inter){
                    for (int row = ty_; row < 46; row += 8)
                        for (int col = tx_; col < 46; col += 32)
                            su[row*46+col] = fmaf(wv2, st[row+4][col+4], su[row*46+col]);
                } else {
                    for (int row = ty_; row < 46; row += 8){
                        int gy = Y0 - 7 + row;
                        int iy = gy + 2 - dy;
                        bool okr = ((unsigned)gy < HV) && ((unsigned)iy < HV);
                        for (int col = tx_; col < 46; col += 32){
                            int gx = X0 - 7 + col;
                            int ix = gx + 2 - dx;
                            if (okr && (unsigned)gx < WV && (unsigned)ix < WV)
                                su[row*46+col] = fmaf(wv2, st[row+4][col+4], su[row*46+col]);
                        }
                    }
                }
            } else if (nt <= 4){
                T4 tf = t4_fwd_dk(stage, n, 54);
                for (int row = ty_; row < 50; row += 8){
                    int gy = Y0 - 9 + row;
                    bool iny = (unsigned)gy < HV;
                    for (int col = tx_; col < 50; col += 32){
                        int gx = X0 - 9 + col;
                        float a2 = 0.f;
                        if (inter || (iny && (unsigned)gx < WV)) a2 = w2*c4(&st[row][col], tf, 0.f);
                        sbuf[row*50+col] = a2;
                    }
                }
                __syncthreads();
                T4 ta = t4_adj_dk(stage, n, 50);
                for (int row = ty_; row < 46; row += 8){
                    int gy = Y0 - 7 + row;
                    bool iny = (unsigned)gy < HV;
                    for (int col = tx_; col < 46; col += 32){
                        int gx = X0 - 7 + col;
                        if (inter || (iny && (unsigned)gx < WV))
                            su[row*46+col] = c4(sbuf + row*50 + col, ta, su[row*46+col]);
                    }
                }
                __syncthreads();
            } else {
                for (int row = ty_; row < 50; row += 8){
                    int gy = Y0 - 9 + row;
                    bool iny = (unsigned)gy < HV;
                    for (int col = tx_; col < 50; col += 32){
                        int gx = X0 - 9 + col;
                        float a2 = 0.f;
                        if (inter || (iny && (unsigned)gx < WV)) a2 = w2*cg_fwd_dk(&st[row][col], stage, n, nt, 54, 0.f);
                        sbuf[row*50+col] = a2;
                    }
                }
                __syncthreads();
                for (int row = ty_; row < 46; row += 8){
                    int gy = Y0 - 7 + row;
                    bool iny = (unsigned)gy < HV;
                    for (int col = tx_; col < 46; col += 32){
                        int gx = X0 - 7 + col;
                        if (inter || (iny && (unsigned)gx < WV))
                            su[row*46+col] = cg_adj_dk(sbuf + row*50 + col, stage, n, nt, 50, su[row*46+col]);
                    }
                }
                __syncthreads();
            }
        }
        __syncthreads();
    }

    float acc[4] = {0,0,0,0};
    int rbase = ty_*4;
    if (fastD){
        for (int v = 0; v < 15; v++){
            float win[18];
            #pragma unroll
            for (int j = 0; j < 18; j++) win[j] = st[rbase+j][tx_+v];
            #pragma unroll
            for (int u = 0; u < 15; u++){
                float kv = sk[u*15+v];
                #pragma unroll
                for (int q = 0; q < 4; q++) acc[q] = fmaf(kv, win[u+q], acc[q]);
            }
        }
        float sc = g_scale1[stage];
        #pragma unroll
        for (int q = 0; q < 4; q++) acc[q] *= sc;
    } else {
        for (int v = 0; v < 15; v++){
            float win[18];
            #pragma unroll
            for (int j = 0; j < 18; j++) win[j] = su[(rbase+j)*46 + tx_+v];
            #pragma unroll
            for (int u = 0; u < 15; u++){
                float kv = sk[u*15+v];
                #pragma unroll
                for (int q = 0; q < 4; q++) acc[q] = fmaf(kv, win[u+q], acc[q]);
            }
        }
        __syncthreads();
    }

    // ---- regularizer term ----
    if (inter && p2){
        int nt4 = g_Snt4[stage];
        #pragma unroll
        for (int q = 0; q < 4; q++){
            const float* base = &sx[rbase+q+4][tx_+4];
            float a2 = acc[q];
            for (int t = 0; t < nt4; t += 4){
                a2 = fmaf(sSv[t],   base[sSo[t]],   a2);
                a2 = fmaf(sSv[t+1], base[sSo[t+1]], a2);
                a2 = fmaf(sSv[t+2], base[sSo[t+2]], a2);
                a2 = fmaf(sSv[t+3], base[sSo[t+3]], a2);
            }
            acc[q] = a2;
        }
        if (csrc){
            const float* cp = csrc + z*NPIX;
            #pragma unroll
            for (int q = 0; q < 4; q++)
                acc[q] -= cp[(Y0+rbase+q)*WV + X0 + tx_];
        }
    } else {
        for (int m = 0; m < 5; m++){
            float wm = rkw[stage*5+m];
            float pm = rpow[stage*5+m];
            float wp = wm*pm;
            int nt = g_rknt[stage][m];
            float* sph = pool + m*1296;
            const float* tg = tgt ? (tgt + (b*5+m)*CN + c*NPIX) : nullptr;
            float* vd = vdst + (b*5+m)*CN + c*NPIX;
            if (nt <= 4){
                T4 tf = t4_fwd_rk(stage, m, 40);
                for (int row = ty_; row < 36; row += 8){
                    int gy = Y0 - 2 + row;
                    bool iny = (unsigned)gy < HV;
                    bool rin = (row >= 2 && row < 34);
                    for (int col = tx_; col < 36; col += 32){
                        int gx = X0 - 2 + col;
                        float ph = 0.f;
                        if (iny && (unsigned)gx < WV){
                            float vv = c4(&sx[row][col], tf, 0.f);
                            int gi = gy*WV + gx;
                            if (tg) vv -= tg[gi];
                            if (p2){
                                ph = wp*sgnf(vv)*(fabsf(vv)+EPSF);
                            } else {
                                ph = wp*sgnf(vv)*powx(fabsf(vv)+EPSF, pm-1.f);
                                if (rin && col >= 2 && col < 34) vd[gi] = vv;
                            }
                        }
                        sph[row*36+col] = ph;
                    }
                }
            } else {
                for (int row = ty_; row < 36; row += 8){
                    int gy = Y0 - 2 + row;
                    bool iny = (unsigned)gy < HV;
                    bool rin = (row >= 2 && row < 34);
                    for (int col = tx_; col < 36; col += 32){
                        int gx = X0 - 2 + col;
                        float ph = 0.f;
                        if (iny && (unsigned)gx < WV){
                            float vv = cg_fwd_rk(&sx[row][col], stage, m, nt, 40, 0.f);
                            int gi = gy*WV + gx;
                            if (tg) vv -= tg[gi];
                            if (p2){
                                ph = wp*sgnf(vv)*(fabsf(vv)+EPSF);
                            } else {
                                ph = wp*sgnf(vv)*powx(fabsf(vv)+EPSF, pm-1.f);
                                if (rin && col >= 2 && col < 34) vd[gi] = vv;
                            }
                        }
                        sph[row*36+col] = ph;
                    }
                }
            }
        }
        __syncthreads();
        for (int m = 0; m < 5; m++){
            int nt = g_rknt[stage][m];
            const float* sph = pool + m*1296;
            if (nt <= 4){
                T4 ta = t4_adj_rk(stage, m, 36);
                #pragma unroll
                for (int q = 0; q < 4; q++)
                    acc[q] = c4(sph + (rbase+q)*36 + tx_, ta, acc[q]);
            } else {
                for (int q = 0; q < 4; q++)
                    acc[q] = cg_adj_rk(sph + (rbase+q)*36 + tx_, stage, m, nt, 36, acc[q]);
            }
        }
    }

    float* ro = rdst + z*NPIX;
    float ss = 0.f;
    #pragma unroll
    for (int q = 0; q < 4; q++){
        ro[(Y0+rbase+q)*WV + X0 + tx_] = -acc[q];
        ss = fmaf(acc[q], acc[q], ss);
    }
    __syncthreads();
    sh[tid] = ss; __syncthreads();
    for (int o = 128; o; o >>= 1){ if (tid < o) sh[tid] += sh[tid+o]; __syncthreads(); }
    if (tid == 0) g_partR[b*768 + c*256 + blockIdx.y*16 + blockIdx.x] = sh[0];
}

// ---------------- prior targets + c-term ----------------
__global__ void __launch_bounds__(256)
k_prior(const float* __restrict__ xsrc, float* __restrict__ dst, float* __restrict__ cdst,
        const float* __restrict__ thr,
        const float* __restrict__ rkw, const float* __restrict__ rpow, int stage)
{
    int z = blockIdx.z; int b = z/CV, c = z - b*CV;
    __shared__ float sxx[1600];
    __shared__ float pool[6480];
    int tx_ = threadIdx.x, ty_ = threadIdx.y;
    int tid = ty_*32 + tx_;
    int X0 = blockIdx.x*32, Y0 = blockIdx.y*32;
    const float* xp = xsrc + z*NPIX;
    for (int row = ty_; row < 40; row += 8){
        int gy = Y0-4+row;
        bool iny = (unsigned)gy < HV;
        for (int col = tx_; col < 40; col += 32){
            int gx = X0-4+col;
            sxx[row*40+col] = (iny && (unsigned)gx < WV) ? xp[gy*WV+gx] : 0.f;
        }
    }
    __syncthreads();
    int rbase = ty_*4;
    int gxo = X0 + tx_;
    for (int m = 0; m < 5; m++){
        int nt = g_rknt[stage][m];
        float th = thr[m];
        float wp = rkw[stage*5+m]*rpow[stage*5+m];
        float* sph = pool + m*1296;
        T4 tf = t4_fwd_rk(stage, m, 40);
        for (int row = ty_; row < 36; row += 8){
            int gy = Y0-2+row;
            bool iny = (unsigned)gy < HV;
            bool rin = (row >= 2 && row < 34);
            for (int col = tx_; col < 36; col += 32){
                int gx = X0-2+col;
                float shr = 0.f;
                if (iny && (unsigned)gx < WV){
                    float v;
                    if (nt <= 4) v = c4(&sxx[row*40+col], tf, 0.f);
                    else v = cg_fwd_rk(&sxx[row*40+col], stage, m, nt, 40, 0.f);
                    shr = sgnf(v)*fmaxf(fabsf(v)-th, 0.f);
                    if (rin && col >= 2 && col < 34)
                        dst[(b*5+m)*CN + c*NPIX + gy*WV + gx] = shr;
                }
                sph[row*36+col] = wp*shr;
            }
        }
    }
    __syncthreads();
    float cacc[4] = {0,0,0,0};
    for (int m = 0; m < 5; m++){
        int nt = g_rknt[stage][m];
        const float* sph = pool + m*1296;
        if (nt <= 4){
            T4 ta = t4_adj_rk(stage, m, 36);
            #pragma unroll
            for (int q = 0; q < 4; q++)
                cacc[q] = c4(sph + (rbase+q)*36 + tx_, ta, cacc[q]);
        } else {
            for (int q = 0; q < 4; q++)
                cacc[q] = cg_adj_rk(sph + (rbase+q)*36 + tx_, stage, m, nt, 36, cacc[q]);
        }
    }
    #pragma unroll
    for (int q = 0; q < 4; q++)
        cdst[z*NPIX + (Y0+rbase+q)*WV + gxo] = cacc[q];
}

// ---------------- bilateral grid (coalesced splat, folded x+alpha*p) ----------------
__global__ void __launch_bounds__(256)
k_splat(const float* __restrict__ x, const float* __restrict__ p,
        float* __restrict__ grid, int slot){
    int pcgy = blockIdx.x;
    int gy = pcgy & 63;
    int pc = pcgy >> 6;
    int b = pc / CV;
    int tid = threadIdx.x;
    __shared__ float srow[4096];
    __shared__ float sh[256], sh2[256], s_alpha;
    float al = alpha_reduce(b, slot, tid, sh, sh2, &s_alpha);
    const float* xp = x + pc*NPIX + (gy*8)*WV;
    const float* pq = p + pc*NPIX + (gy*8)*WV;
    for (int i = tid; i < 4096; i += 256) srow[i] = fmaf(al, pq[i], xp[i]);
    __syncthreads();
    if (tid < 64){
        int gx = tid;
        float bv[NBIN], bw[NBIN];
        #pragma unroll
        for (int z = 0; z < NBIN; z++){ bv[z] = 0.f; bw[z] = 0.f; }
        for (int dy = 0; dy < 8; dy++)
            for (int dx = 0; dx < 8; dx++){
                float I = srow[dy*512 + gx*8+dx];
                float Ic = fminf(fmaxf(I, 0.f), 1.f);
                int zi = (int)rintf(Ic * (float)(NBIN-1));
                zi = max(0, min(NBIN-1, zi));
                bv[zi] += Ic; bw[zi] += 1.f;
            }
        float* gp = grid + ((long)pcgy*64 + gx)*NBIN*2;
        #pragma unroll
        for (int z = 0; z < NBIN; z++){ gp[z*2] = bv[z]; gp[z*2+1] = bw[z]; }
    }
}

// fused separable grid filter: y-conv (11) -> x-conv (11) -> z-conv (5), one launch.
__global__ void __launch_bounds__(256)
k_bconv(const float* __restrict__ gin, float* __restrict__ gout,
        const float* __restrict__ fs, const float* __restrict__ fr)
{
    int blk = blockIdx.x;
    int txt = blk & 7; int tyt = (blk >> 3) & 7; int pc = blk >> 6;
    int Y0 = tyt*8, X0 = txt*8;
    __shared__ float sin[18*18*18];
    __shared__ float sy [8*18*18];
    __shared__ float sxz[8*8*18];
    __shared__ float sfs[11], sfr[5];
    int tid = threadIdx.x;
    const float* gp = gin + (long)pc*(GH*GW*NBIN*2);
    for (int i = tid; i < 18*18*18; i += 256){
        int k = i % 18; int rc = i / 18;
        int c0 = rc % 18, r0 = rc / 18;
        int gy = Y0 - 5 + r0, gx = X0 - 5 + c0;
        float v = 0.f;
        if ((unsigned)gy < GH && (unsigned)gx < GW)
            v = gp[(gy*GW + gx)*18 + k];
        sin[i] = v;
    }
    if (tid < 11) sfs[tid] = fs[tid];
    if (tid < 5)  sfr[tid] = fr[tid];
    __syncthreads();
    for (int i = tid; i < 8*18*18; i += 256){
        int k = i % 18; int rc = i / 18;
        int c0 = rc % 18, r0 = rc / 18;
        const float* bp = sin + (r0*18 + c0)*18 + k;
        float s = 0.f;
        #pragma unroll
        for (int t = 0; t < 11; t++) s = fmaf(sfs[t], bp[t*324], s);
        sy[i] = s;
    }
    __syncthreads();
    for (int i = tid; i < 8*8*18; i += 256){
        int k = i % 18; int rc = i / 18;
        int c0 = rc % 8, r0 = rc / 8;
        const float* bp = sy + (r0*18 + c0)*18 + k;
        float s = 0.f;
        #pragma unroll
        for (int t = 0; t < 11; t++) s = fmaf(sfs[t], bp[t*18], s);
        sxz[i] = s;
    }
    __syncthreads();
    float* go = gout + (long)pc*(GH*GW*NBIN*2);
    for (int i = tid; i < 8*8*18; i += 256){
        int k = i % 18; int rc = i / 18;
        int ch = k & 1; int zz = k >> 1;
        const float* bp = sxz + rc*18 + ch;
        float s = 0.f;
        #pragma unroll
        for (int t = 0; t < 5; t++){
            int cc = zz + t - 2;
            if ((unsigned)cc < NBIN) s = fmaf(sfr[t], bp[cc*2], s);
        }
        int r0 = rc / 8, c0 = rc % 8;
        go[((Y0+r0)*GW + X0+c0)*18 + k] = s;
    }
}

// slice with folded x+alpha*p input; writes result to xout
__global__ void k_slice(const float* __restrict__ xsrc, const float* __restrict__ psrc,
                        float* __restrict__ xout, const float* __restrict__ grid, int slot){
    int i = blockIdx.x*blockDim.x + threadIdx.x;
    int tid = threadIdx.x;
    int pc = i / NPIX;
    int b = pc / CV;
    __shared__ float sh[256], sh2[256], s_alpha;
    float al = alpha_reduce(b, slot, tid, sh, sh2, &s_alpha);
    if (i >= BCN) return;
    int pix = i - pc*NPIX;
    int y = pix / WV, xx = pix - y*WV;
    float I = fmaf(al, psrc[i], xsrc[i]);
    float Ic = fminf(fmaxf(I, 0.f), 1.f);
    float yf = (float)y * 0.125f;
    float xf = (float)xx * 0.125f;
    float zf = Ic * (float)(NBIN-1);
    int y0 = max(0, min(GH-1, (int)floorf(yf)));  int y1 = min(y0+1, GH-1);
    float wy = fminf(fmaxf(yf - (float)y0, 0.f), 1.f);
    int x0 = max(0, min(GW-1, (int)floorf(xf)));  int x1 = min(x0+1, GW-1);
    float wx = fminf(fmaxf(xf - (float)x0, 0.f), 1.f);
    int z0 = max(0, min(NBIN-1, (int)floorf(zf))); int z1 = min(z0+1, NBIN-1);
    float wz = fminf(fmaxf(zf - (float)z0, 0.f), 1.f);
    const float* gp = grid + (long)pc*GH*GW*NBIN*2;
    float a0 = 0.f, a1 = 0.f;
    int ys[2]   = {y0, y1};  float wys[2] = {1.f-wy, wy};
    int xs[2]   = {x0, x1};  float wxs[2] = {1.f-wx, wx};
    int zs[2]   = {z0, z1};  float wzs[2] = {1.f-wz, wz};
    for (int a = 0; a < 2; a++)
        for (int bb = 0; bb < 2; bb++)
            for (int cc = 0; cc < 2; cc++){
                float w = wys[a]*wxs[bb]*wzs[cc];
                int idx = (((ys[a]*GW) + xs[bb])*NBIN + zs[cc])*2;
                a0 = fmaf(w, gp[idx], a0);
                a1 = fmaf(w, gp[idx+1], a1);
            }
    xout[i] = a0 / (a1 + 1e-8f);
}

// ---------------- host orchestration ----------------
extern "C" void kernel_launch(void* const* d_in, const int* in_sizes, int n_in,
                              void* d_out, int out_size)
{
    const float* blurred = (const float*)d_in[0];
    const float* kern    = (const float*)d_in[1];
    const float* dks     = (const float*)d_in[2];
    const float* dkw     = (const float*)d_in[3];
    const float* rks     = (const float*)d_in[4];
    const float* rkw     = (const float*)d_in[5];
    const float* rpow    = (const float*)d_in[6];
    const float* fs      = (const float*)d_in[7];
    const float* fr      = (const float*)d_in[8];
    const float* thr     = (const float*)d_in[9];
    const int NCG = 5;

    float *px, *px2, *pr, *pp, *pp2, *pt, *pt2, *ptp, *pv, *ptg, *pgA, *pgB;
    cudaGetSymbolAddress((void**)&px,  g_x);
    cudaGetSymbolAddress((void**)&px2, g_x2);
    cudaGetSymbolAddress((void**)&pr,  g_r);
    cudaGetSymbolAddress((void**)&pp,  g_p);
    cudaGetSymbolAddress((void**)&pp2, g_p2);
    cudaGetSymbolAddress((void**)&pt,  g_t);
    cudaGetSymbolAddress((void**)&pt2, g_t2);
    cudaGetSymbolAddress((void**)&ptp, g_tp);
    cudaGetSymbolAddress((void**)&pv,  g_v);
    cudaGetSymbolAddress((void**)&ptg, g_tgt);
    cudaGetSymbolAddress((void**)&pgA, g_gridA);
    cudaGetSymbolAddress((void**)&pgB, g_gridB);

    dim3 cb(32, 8);
    dim3 cg15(16, 4, BV*CV);   // 32x128 tiles, RY=16
    dim3 cg32(16, 16, BV*CV);  // 32x32 tiles (gradfull/prior)
    int EW = (BCN + 255)/256;

    k_prep<<<1,32>>>(dks, dkw, rks, rkw, rpow);

    const float* s0x = nullptr; const float* s0p = nullptr; int s0slot = 0;
    auto cgrun = [&](int stage, const float* tgt, const float* cbuf,
                     const float* xin, float* xfinal){
        float* tcur = pt;   float* tnxt = pt2;
        float* pcur = pp;   float* pnxt = pp2;
        k_conv15<<<cg15,cb>>>(xin, tcur, kern, blurred);
        float* xcur = (xin == px) ? px2 : px;
        k_gradfull<<<cg32,cb>>>(xin, pcur, tcur, ptp, xcur, tnxt, tgt, cbuf, pr, pv,
                                kern, rkw, rpow, stage, 0, 1);
        { float* q = tcur; tcur = tnxt; tnxt = q; }
        for (int it = 0; it < NCG; it++){
            int rs = it & 1, ws = rs ^ 1;
            k_pstep<<<cg15,cb>>>(pcur, pnxt, ptp, pr, kern, rkw, rpow, stage, it == 0, rs);
            if (it == NCG-1){
                if (xfinal){
                    k_axpy_final<<<dim3(256,BV),256>>>(xcur, pnxt, xfinal, ws);
                } else {
                    s0x = xcur; s0p = pnxt; s0slot = ws;
                }
            } else {
                float* xd = (xcur == px) ? px2 : px;
                k_gradfull<<<cg32,cb>>>(xcur, pnxt, tcur, ptp, xd, tnxt, tgt, cbuf, pr, pv,
                                        kern, rkw, rpow, stage, ws, 0);
                xcur = xd;
                { float* q = tcur; tcur = tnxt; tnxt = q; }
            }
            { float* q = pcur; pcur = pnxt; pnxt = q; }
        }
    };

    // Stage 0 (targets = 0, c = 0); final axpy deferred into splat/slice
    cgrun(0, nullptr, nullptr, blurred, nullptr);

    float* xbi = (s0x == px) ? px2 : px;
    k_splat<<<BV*CV*GH, 256>>>(s0x, s0p, pgA, s0slot);
    k_bconv<<<BV*CV*64, 256>>>(pgA, pgB, fs, fr);
    k_slice<<<EW,256>>>(s0x, s0p, xbi, pgB, s0slot);

    k_prior<<<cg32,cb>>>(xbi, ptg, pv, thr, rkw, rpow, 1);
    cgrun(1, ptg, pv, xbi, (float*)d_out);
}

// round 17
// speedup vs baseline: 1.1347x; 1.0576x over previous
#include <cuda_runtime.h>

#define BV 2
#define CV 3
#define HV 512
#define WV 512
#define NPIX (HV*WV)
#define CN (CV*NPIX)
#define BCN (BV*CN)
#define GH 64
#define GW 64
#define NBIN 9
#define NGRID (BV*CV*GH*GW*NBIN*2)
#define EPSF 1e-8f
#define CG_TOL 1e-4f

// ---------------- scratch (device globals; no allocation) ----------------
__device__ float g_x[BCN], g_x2[BCN];
__device__ float g_r[BCN];
__device__ float g_p[BCN], g_p2[BCN];
__device__ float g_t[BCN], g_t2[BCN];
__device__ float g_tp[BCN];
__device__ float g_v[BV*5*CN];        // reused: [0..BCN) holds c-term for stage 1
__device__ float g_tgt[BV*5*CN];
__device__ float g_gridA[NGRID], g_gridB[NGRID];
__device__ float g_partN[BV*192];
__device__ float g_partDf[BV*192];
__device__ float g_partR[BV*768];
__device__ float g_r0[BV];
__device__ float g_rnS[2][BV];
__device__ int   g_doneS[2][BV];

// sparse tap metadata, zero-padded (exact: fmaf(0,x,a)==a for finite x)
__device__ int   g_dknt[2][6];
__device__ int   g_dkdy[2][6][25];
__device__ int   g_dkdx[2][6][25];
__device__ float g_dkv [2][6][25];
__device__ float g_dkw2[2][6];
__device__ int   g_rknt[2][5];
__device__ int   g_rkdy[2][5][25];
__device__ int   g_rkdx[2][5][25];
__device__ float g_rkv [2][5][25];
__device__ int   g_fastDk[2];
__device__ float g_scale1[2];
__device__ int   g_allp2[2];
__device__ int   g_fusedDen[2];
__device__ int   g_Snt4[2];
__device__ float g_Sv[2][84];
__device__ int   g_So40[2][84];

__device__ __forceinline__ float powx(float a, float e){
    if (e == 0.0f) return 1.0f;
    if (e == 1.0f) return a;
    return powf(a, e);
}
__device__ __forceinline__ float sgnf(float v){
    return (v > 0.f) ? 1.f : ((v < 0.f) ? -1.f : 0.f);
}

struct T4 { float v0,v1,v2,v3; int o0,o1,o2,o3; };
__device__ __forceinline__ T4 t4_fwd_rk(int s,int m,int st){
    T4 t;
    t.v0=g_rkv[s][m][0]; t.v1=g_rkv[s][m][1]; t.v2=g_rkv[s][m][2]; t.v3=g_rkv[s][m][3];
    t.o0=g_rkdy[s][m][0]*st+g_rkdx[s][m][0]; t.o1=g_rkdy[s][m][1]*st+g_rkdx[s][m][1];
    t.o2=g_rkdy[s][m][2]*st+g_rkdx[s][m][2]; t.o3=g_rkdy[s][m][3]*st+g_rkdx[s][m][3];
    return t;
}
__device__ __forceinline__ T4 t4_adj_rk(int s,int m,int st){
    T4 t;
    t.v0=g_rkv[s][m][0]; t.v1=g_rkv[s][m][1]; t.v2=g_rkv[s][m][2]; t.v3=g_rkv[s][m][3];
    t.o0=(4-g_rkdy[s][m][0])*st+(4-g_rkdx[s][m][0]); t.o1=(4-g_rkdy[s][m][1])*st+(4-g_rkdx[s][m][1]);
    t.o2=(4-g_rkdy[s][m][2])*st+(4-g_rkdx[s][m][2]); t.o3=(4-g_rkdy[s][m][3])*st+(4-g_rkdx[s][m][3]);
    return t;
}
__device__ __forceinline__ T4 t4_fwd_dk(int s,int n,int st){
    T4 t;
    t.v0=g_dkv[s][n][0]; t.v1=g_dkv[s][n][1]; t.v2=g_dkv[s][n][2]; t.v3=g_dkv[s][n][3];
    t.o0=g_dkdy[s][n][0]*st+g_dkdx[s][n][0]; t.o1=g_dkdy[s][n][1]*st+g_dkdx[s][n][1];
    t.o2=g_dkdy[s][n][2]*st+g_dkdx[s][n][2]; t.o3=g_dkdy[s][n][3]*st+g_dkdx[s][n][3];
    return t;
}
__device__ __forceinline__ T4 t4_adj_dk(int s,int n,int st){
    T4 t;
    t.v0=g_dkv[s][n][0]; t.v1=g_dkv[s][n][1]; t.v2=g_dkv[s][n][2]; t.v3=g_dkv[s][n][3];
    t.o0=(4-g_dkdy[s][n][0])*st+(4-g_dkdx[s][n][0]); t.o1=(4-g_dkdy[s][n][1])*st+(4-g_dkdx[s][n][1]);
    t.o2=(4-g_dkdy[s][n][2])*st+(4-g_dkdx[s][n][2]); t.o3=(4-g_dkdy[s][n][3])*st+(4-g_dkdx[s][n][3]);
    return t;
}
__device__ __forceinline__ float c4(const float* p, const T4& t, float a){
    a = fmaf(t.v0, p[t.o0], a);
    a = fmaf(t.v1, p[t.o1], a);
    a = fmaf(t.v2, p[t.o2], a);
    a = fmaf(t.v3, p[t.o3], a);
    return a;
}
__device__ __forceinline__ float cg_fwd_dk(const float* p,int s,int n,int nt,int st,float a){
    for (int t = 0; t < nt; t++) a = fmaf(g_dkv[s][n][t], p[g_dkdy[s][n][t]*st+g_dkdx[s][n][t]], a);
    return a;
}
__device__ __forceinline__ float cg_adj_dk(const float* p,int s,int n,int nt,int st,float a){
    for (int t = 0; t < nt; t++) a = fmaf(g_dkv[s][n][t], p[(4-g_dkdy[s][n][t])*st+(4-g_dkdx[s][n][t])], a);
    return a;
}
__device__ __forceinline__ float cg_fwd_rk(const float* p,int s,int m,int nt,int st,float a){
    for (int t = 0; t < nt; t++) a = fmaf(g_rkv[s][m][t], p[g_rkdy[s][m][t]*st+g_rkdx[s][m][t]], a);
    return a;
}
__device__ __forceinline__ float cg_adj_rk(const float* p,int s,int m,int nt,int st,float a){
    for (int t = 0; t < nt; t++) a = fmaf(g_rkv[s][m][t], p[(4-g_rkdy[s][m][t])*st+(4-g_rkdx[s][m][t])], a);
    return a;
}
// deterministic alpha reduction over 192-slot partials (identical everywhere)
__device__ __forceinline__ float alpha_reduce(int b, int slot, int tid,
                                              float* sh, float* sh2, float* s_alpha)
{
    float sn = 0.f, sd = 0.f;
    if (tid < 64){
        sn = g_partN [b*192+tid] + g_partN [b*192+64+tid] + g_partN [b*192+128+tid];
        sd = g_partDf[b*192+tid] + g_partDf[b*192+64+tid] + g_partDf[b*192+128+tid];
    }
    sh[tid] = sn; sh2[tid] = sd; __syncthreads();
    for (int o = 128; o; o >>= 1){
        if (tid < o){ sh[tid] += sh[tid+o]; sh2[tid] += sh2[tid+o]; }
        __syncthreads();
    }
    if (tid == 0){
        int dn = g_doneS[slot][b];
        *s_alpha = dn ? 0.f : sh[0]/(sh2[0] + 1e-12f);
    }
    __syncthreads();
    return *s_alpha;
}

// ---------------- prep ----------------
__global__ void k_prep(const float* __restrict__ dks, const float* __restrict__ dkw,
                       const float* __restrict__ rks, const float* __restrict__ rkw,
                       const float* __restrict__ rpow)
{
    if (threadIdx.x != 0 || blockIdx.x != 0) return;
    for (int s = 0; s < 2; s++){
        int fast = 1, center1 = 1; float sc1 = 0.f;
        for (int n = 0; n < 6; n++){
            float w2 = 2.f*dkw[s*6+n];
            g_dkw2[s][n] = w2;
            int cnt = 0;
            for (int j = 0; j < 25; j++){
                float v = dks[(s*6+n)*25 + j];
                if (v != 0.f){
                    g_dkdy[s][n][cnt] = j/5; g_dkdx[s][n][cnt] = j%5;
                    g_dkv [s][n][cnt] = v; cnt++;
                }
            }
            g_dknt[s][n] = cnt;
            for (int j = cnt; j < 25; j++){ g_dkdy[s][n][j]=0; g_dkdx[s][n][j]=0; g_dkv[s][n][j]=0.f; }
            if (w2 != 0.f){
                if (cnt == 1){
                    sc1 += w2*g_dkv[s][n][0]*g_dkv[s][n][0];
                    if (g_dkdy[s][n][0] != 2 || g_dkdx[s][n][0] != 2) center1 = 0;
                } else { fast = 0; center1 = 0; }
            }
        }
        g_fastDk[s] = fast;
        g_scale1[s] = sc1;
        int p2 = 1;
        for (int m = 0; m < 5; m++){
            if (rpow[s*5+m] != 2.0f) p2 = 0;
            int cnt = 0;
            for (int j = 0; j < 25; j++){
                float v = rks[(s*5+m)*25 + j];
                if (v != 0.f){
                    g_rkdy[s][m][cnt] = j/5; g_rkdx[s][m][cnt] = j%5;
                    g_rkv [s][m][cnt] = v; cnt++;
                }
            }
            g_rknt[s][m] = cnt;
            for (int j = cnt; j < 25; j++){ g_rkdy[s][m][j]=0; g_rkdx[s][m][j]=0; g_rkv[s][m][j]=0.f; }
        }
        g_allp2[s] = p2;
        g_fusedDen[s] = p2 && center1;

        float Sbuf[81];
        for (int j = 0; j < 81; j++) Sbuf[j] = 0.f;
        for (int m = 0; m < 5; m++){
            float wp = rkw[s*5+m]*rpow[s*5+m];
            int nt = g_rknt[s][m];
            for (int t1 = 0; t1 < nt; t1++)
                for (int t2 = 0; t2 < nt; t2++){
                    int ody = g_rkdy[s][m][t1] - g_rkdy[s][m][t2];
                    int odx = g_rkdx[s][m][t1] - g_rkdx[s][m][t2];
                    Sbuf[(ody+4)*9 + (odx+4)] += wp*g_rkv[s][m][t1]*g_rkv[s][m][t2];
                }
        }
        int cnt = 0;
        for (int j = 0; j < 81; j++){
            if (Sbuf[j] != 0.f){
                g_Sv[s][cnt] = Sbuf[j];
                g_So40[s][cnt] = (j/9 - 4)*40 + (j%9 - 4);
                cnt++;
            }
        }
        while (cnt & 3){ g_Sv[s][cnt] = 0.f; g_So40[s][cnt] = 0; cnt++; }
        g_Snt4[s] = cnt;
    }
}

// ---------------- plain 15x15 conv - sub (CG init only), 32x128 tile, RY=16 ---------
__global__ void __launch_bounds__(256)
k_conv15(const float* __restrict__ src, float* __restrict__ dst,
         const float* __restrict__ kern, const float* __restrict__ sub)
{
    int z = blockIdx.z; int b = z / CV;
    __shared__ float tile[142][46];
    __shared__ float sk[225];
    const float* sp = src + z*NPIX;
    int X0 = blockIdx.x*32, Y0 = blockIdx.y*128;
    int x0 = X0 - 7, y0 = Y0 - 7;
    int tx_ = threadIdx.x, ty_ = threadIdx.y;
    int tid = ty_*32 + tx_;
    bool inter = (Y0 >= 7) && (Y0 + 135 <= HV) && (X0 >= 7) && (X0 + 39 <= WV);
    if (inter){
        for (int row = ty_; row < 142; row += 8){
            const float* rp = sp + (y0+row)*WV + x0;
            for (int col = tx_; col < 46; col += 32) tile[row][col] = rp[col];
        }
    } else {
        for (int row = ty_; row < 142; row += 8){
            int gy = y0 + row;
            bool iny = (unsigned)gy < HV;
            for (int col = tx_; col < 46; col += 32){
                int gx = x0 + col;
                tile[row][col] = (iny && (unsigned)gx < WV) ? sp[gy*WV+gx] : 0.f;
            }
        }
    }
    const float* kb = kern + b*225;
    for (int i = tid; i < 225; i += 256) sk[i] = kb[i];
    __syncthreads();
    float acc[16];
    #pragma unroll
    for (int q = 0; q < 16; q++) acc[q] = 0.f;
    int rbase = ty_*16;
    for (int v = 0; v < 15; v++){
        float win[30];
        #pragma unroll
        for (int j = 0; j < 30; j++) win[j] = tile[rbase+j][tx_+v];
        #pragma unroll
        for (int u = 0; u < 15; u++){
            float kv = sk[u*15+v];
            #pragma unroll
            for (int q = 0; q < 16; q++) acc[q] = fmaf(kv, win[u+q], acc[q]);
        }
    }
    int gx = X0 + tx_;
    int gyb = Y0 + rbase;
    #pragma unroll
    for (int q = 0; q < 16; q++){
        int oi = z*NPIX + (gyb+q)*WV + gx;
        float o = acc[q];
        if (sub) o -= sub[oi];
        dst[oi] = o;
    }
}

// ---- fused: beta/done + p update + Kp conv + num + den, 32x128 tile, RY=16 ---------
__global__ void __launch_bounds__(256)
k_pstep(const float* __restrict__ pold, float* __restrict__ pnew,
        float* __restrict__ kp, const float* __restrict__ rsrc,
        const float* __restrict__ kern,
        const float* __restrict__ rkw, const float* __restrict__ rpow,
        int stage, int first, int slot)
{
    int z = blockIdx.z; int b = z/CV, c = z - b*CV;
    int tx_ = threadIdx.x, ty_ = threadIdx.y;
    int tid = ty_*32 + tx_;
    __shared__ float pn[142][46];
    __shared__ float sk[225];
    __shared__ float sh[256];
    __shared__ float sh2[256];
    __shared__ float s_beta;
    __shared__ int s_freeze;

    float a = g_partR[b*768+tid] + g_partR[b*768+256+tid] + g_partR[b*768+512+tid];
    sh[tid] = a; __syncthreads();
    for (int o = 128; o; o >>= 1){ if (tid < o) sh[tid] += sh[tid+o]; __syncthreads(); }
    if (tid == 0){
        float nrn = sh[0];
        int done_prev = first ? 0 : g_doneS[slot][b];
        float rn_prev = first ? 1.f : g_rnS[slot][b];
        float r0 = first ? nrn : g_r0[b];
        int conv_now = (!first) && (nrn < CG_TOL*r0);
        s_beta = first ? 0.f : nrn/(rn_prev + 1e-20f);
        s_freeze = first ? 0 : (done_prev | conv_now);
        if (blockIdx.x == 0 && blockIdx.y == 0 && c == 0){
            g_doneS[slot^1][b] = done_prev | conv_now;
            g_rnS[slot^1][b] = done_prev ? rn_prev : nrn;
            if (first) g_r0[b] = nrn;
        }
    }
    __syncthreads();
    int X0 = blockIdx.x*32, Y0 = blockIdx.y*128;
    if (s_freeze){
        const float* pop = pold + z*NPIX;
        float* pno = pnew + z*NPIX;
        for (int row = ty_; row < 128; row += 8){
            int gi = (Y0+row)*WV + X0 + tx_;
            pno[gi] = pop[gi];
        }
        return;
    }
    float beta = s_beta;
    const float* rp = rsrc + z*NPIX;
    const float* pop = pold + z*NPIX;
    float* pno = pnew + z*NPIX;
    int x0 = X0 - 7, y0 = Y0 - 7;
    bool inter = (Y0 >= 7) && (Y0 + 135 <= HV) && (X0 >= 7) && (X0 + 39 <= WV);
    float s = 0.f;
    if (inter){
        for (int row = ty_; row < 142; row += 8){
            const float* rr = rp + (y0+row)*WV + x0;
            const float* pr2 = pop + (y0+row)*WV + x0;
            float* pw = pno + (y0+row)*WV + x0;
            bool rin = (row >= 7 && row < 135);
            for (int col = tx_; col < 46; col += 32){
                float rv = rr[col];
                float v = first ? rv : fmaf(beta, pr2[col], rv);
                if (rin && col >= 7 && col < 39){
                    pw[col] = v;
                    s = fmaf(rv, v, s);
                }
                pn[row][col] = v;
            }
        }
    } else {
        for (int row = ty_; row < 142; row += 8){
            int gy = y0 + row;
            bool iny = (unsigned)gy < HV;
            bool rin = (row >= 7 && row < 135);
            for (int col = tx_; col < 46; col += 32){
                int gx = x0 + col;
                float v = 0.f;
                if (iny && (unsigned)gx < WV){
                    int gi = gy*WV + gx;
                    float rv = rp[gi];
                    v = first ? rv : fmaf(beta, pop[gi], rv);
                    if (rin && col >= 7 && col < 39){
                        pno[gi] = v;
                        s = fmaf(rv, v, s);
                    }
                }
                pn[row][col] = v;
            }
        }
    }
    const float* kb = kern + b*225;
    for (int i = tid; i < 225; i += 256) sk[i] = kb[i];
    __syncthreads();
    float acc[16];
    #pragma unroll
    for (int q = 0; q < 16; q++) acc[q] = 0.f;
    int rbase = ty_*16;
    for (int v = 0; v < 15; v++){
        float win[30];
        #pragma unroll
        for (int j = 0; j < 30; j++) win[j] = pn[rbase+j][tx_+v];
        #pragma unroll
        for (int u = 0; u < 15; u++){
            float kv = sk[u*15+v];
            #pragma unroll
            for (int q = 0; q < 16; q++) acc[q] = fmaf(kv, win[u+q], acc[q]);
        }
    }
    float* ko = kp + z*NPIX;
    #pragma unroll
    for (int q = 0; q < 16; q++)
        ko[(Y0+rbase+q)*WV + X0 + tx_] = acc[q];

    // fused denominator (exact: all rpow==2 and data filters are center deltas)
    float sden = 0.f;
    {
        float sc1 = g_scale1[stage];
        #pragma unroll
        for (int q = 0; q < 16; q++) sden = fmaf(sc1*acc[q], acc[q], sden);
        for (int m = 0; m < 5; m++){
            int nt = g_rknt[stage][m];
            float pmv = rpow[stage*5+m];
            float wc = rkw[stage*5+m]*pmv*(pmv-1.f);
            if (nt <= 4){
                T4 tf = t4_fwd_rk(stage, m, 46);
                #pragma unroll
                for (int q = 0; q < 16; q++){
                    float rv = c4(&pn[rbase+q+5][tx_+5], tf, 0.f);
                    sden = fmaf(wc*rv, rv, sden);
                }
            } else {
                for (int q = 0; q < 16; q++){
                    float rv = cg_fwd_rk(&pn[rbase+q+5][tx_+5], stage, m, nt, 46, 0.f);
                    sden = fmaf(wc*rv, rv, sden);
                }
            }
        }
    }
    __syncthreads();
    sh[tid] = s; sh2[tid] = sden; __syncthreads();
    for (int o = 128; o; o >>= 1){
        if (tid < o){ sh[tid] += sh[tid+o]; sh2[tid] += sh2[tid+o]; }
        __syncthreads();
    }
    if (tid == 0){
        g_partN [b*192 + c*64 + blockIdx.y*16 + blockIdx.x] = sh[0];
        g_partDf[b*192 + c*64 + blockIdx.y*16 + blockIdx.x] = sh2[0];
    }
}

// ---------------- final-iteration axpy (stage 1 only) ----------------
__global__ void k_axpy_final(const float* __restrict__ xsrc, const float* __restrict__ psrc,
                             float* __restrict__ xdst, int slot)
{
    int b = blockIdx.y;
    int tid = threadIdx.x;
    __shared__ float sh[256], sh2[256], s_alpha;
    float al = alpha_reduce(b, slot, tid, sh, sh2, &s_alpha);
    const float* xp = xsrc + b*CN;
    const float* pp = psrc + b*CN;
    float* xo = xdst + b*CN;
    for (int i = blockIdx.x*256 + tid; i < CN; i += 65536)
        xo[i] = fmaf(al, pp[i], xp[i]);
}

// ---------------- fused gradient + x/t update + r-norm partial ----------------
// border-first block remap: slow border tiles launch in wave 1.
__global__ void __launch_bounds__(256,5)
k_gradfull(const float* __restrict__ xsrc, const float* __restrict__ psrc,
           const float* __restrict__ tsrc, const float* __restrict__ tpsrc,
           float* __restrict__ xdst, float* __restrict__ tdst,
           const float* __restrict__ tgt, const float* __restrict__ csrc,
           float* __restrict__ rdst, float* __restrict__ vdst,
           const float* __restrict__ kern,
           const float* __restrict__ rkw, const float* __restrict__ rpow,
           int stage, int slot, int first)
{
    int z = blockIdx.z; int b = z/CV, c = z - b*CV;
    int tx_ = threadIdx.x, ty_ = threadIdx.y;
    int tid = ty_*32 + tx_;

    // border-first tile permutation (bijection on 16x16 tiles)
    int L = blockIdx.y*16 + blockIdx.x;
    int bx, by;
    if (L < 16){ by = 0; bx = L; }
    else if (L < 32){ by = 15; bx = L - 16; }
    else if (L < 46){ bx = 0; by = 1 + (L - 32); }
    else if (L < 60){ bx = 15; by = 1 + (L - 46); }
    else { int i2 = L - 60; by = 1 + i2/14; bx = 1 + i2 - (i2/14)*14; }
    int X0 = bx*32, Y0 = by*32;
    int pslot = by*16 + bx;   // same tile->slot map as row-major (bitwise-identical sums)

    int dn = first ? 0 : g_doneS[slot][b];
    if (dn){
        const float* xp = xsrc + z*NPIX;
        const float* tp = tsrc + z*NPIX;
        float* xo = xdst + z*NPIX;
        float* to = tdst + z*NPIX;
        for (int row = ty_; row < 32; row += 8){
            int gi = (Y0+row)*WV + X0 + tx_;
            xo[gi] = xp[gi];
            to[gi] = tp[gi];
        }
        return;
    }

    __shared__ float st[54][54];
    __shared__ float sx[40][40];
    __shared__ float pool[6480];
    __shared__ float sk[225];
    __shared__ float sSv[84];
    __shared__ int   sSo[84];
    __shared__ float sh[256];
    __shared__ float sh2[256];
    __shared__ float s_alpha;

    if (first){
        if (tid == 0) s_alpha = 0.f;
        __syncthreads();
    } else {
        alpha_reduce(b, slot, tid, sh, sh2, &s_alpha);
    }
    float al = s_alpha;

    const float* xp = xsrc + z*NPIX;
    const float* pp = psrc + z*NPIX;
    const float* tp = tsrc + z*NPIX;
    const float* tq = tpsrc + z*NPIX;
    float* xo = xdst + z*NPIX;
    float* to = tdst + z*NPIX;

    bool inter = (Y0 >= 11) && (Y0 + 43 <= HV) && (X0 >= 11) && (X0 + 43 <= WV);
    bool fastD = inter && (g_fastDk[stage] != 0);
    int p2 = g_allp2[stage];
    float* su = pool;
    float* sbuf = pool + 2116;

    if (fastD){
        for (int row = ty_; row < 46; row += 8){
            const float* a1 = tp + (Y0-7+row)*WV + X0-7;
            const float* a2 = tq + (Y0-7+row)*WV + X0-7;
            float* a3 = to + (Y0-7+row)*WV + X0-7;
            bool rin = (row >= 7 && row < 39);
            for (int col = tx_; col < 46; col += 32){
                float v = first ? a1[col] : fmaf(al, a2[col], a1[col]);
                if (rin && col >= 7 && col < 39) a3[col] = v;
                st[row][col] = v;
            }
        }
        for (int row = ty_; row < 40; row += 8){
            const float* a1 = xp + (Y0-4+row)*WV + X0-4;
            const float* a2 = pp + (Y0-4+row)*WV + X0-4;
            float* a3 = xo + (Y0-4+row)*WV + X0-4;
            bool rin = (row >= 4 && row < 36);
            for (int col = tx_; col < 40; col += 32){
                float v = first ? a1[col] : fmaf(al, a2[col], a1[col]);
                if (rin && col >= 4 && col < 36) a3[col] = v;
                sx[row][col] = v;
            }
        }
    } else if (inter){
        for (int row = ty_; row < 54; row += 8){
            const float* a1 = tp + (Y0-11+row)*WV + X0-11;
            const float* a2 = tq + (Y0-11+row)*WV + X0-11;
            float* a3 = to + (Y0-11+row)*WV + X0-11;
            bool rin = (row >= 11 && row < 43);
            for (int col = tx_; col < 54; col += 32){
                float v = first ? a1[col] : fmaf(al, a2[col], a1[col]);
                if (rin && col >= 11 && col < 43) a3[col] = v;
                st[row][col] = v;
            }
        }
        for (int row = ty_; row < 40; row += 8){
            const float* a1 = xp + (Y0-4+row)*WV + X0-4;
            const float* a2 = pp + (Y0-4+row)*WV + X0-4;
            float* a3 = xo + (Y0-4+row)*WV + X0-4;
            bool rin = (row >= 4 && row < 36);
            for (int col = tx_; col < 40; col += 32){
                float v = first ? a1[col] : fmaf(al, a2[col], a1[col]);
                if (rin && col >= 4 && col < 36) a3[col] = v;
                sx[row][col] = v;
            }
        }
    } else {
        for (int row = ty_; row < 54; row += 8){
            int gy = Y0 - 11 + row;
            bool iny = (unsigned)gy < HV;
            bool rin = (row >= 11 && row < 43);
            for (int col = tx_; col < 54; col += 32){
                int gx = X0 - 11 + col;
                float v = 0.f;
                if (iny && (unsigned)gx < WV){
                    int gi = gy*WV + gx;
                    v = first ? tp[gi] : fmaf(al, tq[gi], tp[gi]);
                    if (rin && col >= 11 && col < 43) to[gi] = v;
                }
                st[row][col] = v;
            }
        }
        for (int row = ty_; row < 40; row += 8){
            int gy = Y0 - 4 + row;
            bool iny = (unsigned)gy < HV;
            bool rin = (row >= 4 && row < 36);
            for (int col = tx_; col < 40; col += 32){
                int gx = X0 - 4 + col;
                float v = 0.f;
                if (iny && (unsigned)gx < WV){
                    int gi = gy*WV + gx;
                    v = first ? xp[gi] : fmaf(al, pp[gi], xp[gi]);
                    if (rin && col >= 4 && col < 36) xo[gi] = v;
                }
                sx[row][col] = v;
            }
        }
    }
    const float* kb = kern + b*225;
    for (int i = tid; i < 225; i += 256) sk[i] = kb[224 - i];
    for (int i = tid; i < 84; i += 256){ sSv[i] = g_Sv[stage][i]; sSo[i] = g_So40[stage][i]; }
    if (!fastD)
        for (int i = tid; i < 2116; i += 256) su[i] = 0.f;
    __syncthreads();

    if (!fastD){
        for (int n = 0; n < 6; n++){
            float w2 = g_dkw2[stage][n];
            if (w2 == 0.f) continue;
            int nt = g_dknt[stage][n];
            if (nt == 1){
                int dy = g_dkdy[stage][n][0], dx = g_dkdx[stage][n][0];
                float vv0 = g_dkv[stage][n][0];
                float wv2 = w2*vv0*vv0;
                if (inter){
                    for (int row = ty_; row < 46; row += 8)
                        for (int col = tx_; col < 46; col += 32)
                            su[row*46+col] = fmaf(wv2, st[row+4][col+4], su[row*46+col]);
                } else {
                    for (int row = ty_; row < 46; row += 8){
                        int gy = Y0 - 7 + row;
                        int iy = gy + 2 - dy;
                        bool okr = ((unsigned)gy < HV) && ((unsigned)iy < HV);
                        for (int col = tx_; col < 46; col += 32){
                            int gx = X0 - 7 + col;
                            int ix = gx + 2 - dx;
                            if (okr && (unsigned)gx < WV && (unsigned)ix < WV)
                                su[row*46+col] = fmaf(wv2, st[row+4][col+4], su[row*46+col]);
                        }
                    }
                }
            } else if (nt <= 4){
                T4 tf = t4_fwd_dk(stage, n, 54);
                for (int row = ty_; row < 50; row += 8){
                    int gy = Y0 - 9 + row;
                    bool iny = (unsigned)gy < HV;
                    for (int col = tx_; col < 50; col += 32){
                        int gx = X0 - 9 + col;
                        float a2 = 0.f;
                        if (inter || (iny && (unsigned)gx < WV)) a2 = w2*c4(&st[row][col], tf, 0.f);
                        sbuf[row*50+col] = a2;
                    }
                }
                __syncthreads();
                T4 ta = t4_adj_dk(stage, n, 50);
                for (int row = ty_; row < 46; row += 8){
                    int gy = Y0 - 7 + row;
                    bool iny = (unsigned)gy < HV;
                    for (int col = tx_; col < 46; col += 32){
                        int gx = X0 - 7 + col;
                        if (inter || (iny && (unsigned)gx < WV))
                            su[row*46+col] = c4(sbuf + row*50 + col, ta, su[row*46+col]);
                    }
                }
                __syncthreads();
            } else {
                for (int row = ty_; row < 50; row += 8){
                    int gy = Y0 - 9 + row;
                    bool iny = (unsigned)gy < HV;
                    for (int col = tx_; col < 50; col += 32){
                        int gx = X0 - 9 + col;
                        float a2 = 0.f;
                        if (inter || (iny && (unsigned)gx < WV)) a2 = w2*cg_fwd_dk(&st[row][col], stage, n, nt, 54, 0.f);
                        sbuf[row*50+col] = a2;
                    }
                }
                __syncthreads();
                for (int row = ty_; row < 46; row += 8){
                    int gy = Y0 - 7 + row;
                    bool iny = (unsigned)gy < HV;
                    for (int col = tx_; col < 46; col += 32){
                        int gx = X0 - 7 + col;
                        if (inter || (iny && (unsigned)gx < WV))
                            su[row*46+col] = cg_adj_dk(sbuf + row*50 + col, stage, n, nt, 50, su[row*46+col]);
                    }
                }
                __syncthreads();
            }
        }
        __syncthreads();
    }

    float acc[4] = {0,0,0,0};
    int rbase = ty_*4;
    if (fastD){
        for (int v = 0; v < 15; v++){
            float win[18];
            #pragma unroll
            for (int j = 0; j < 18; j++) win[j] = st[rbase+j][tx_+v];
            #pragma unroll
            for (int u = 0; u < 15; u++){
                float kv = sk[u*15+v];
                #pragma unroll
                for (int q = 0; q < 4; q++) acc[q] = fmaf(kv, win[u+q], acc[q]);
            }
        }
        float sc = g_scale1[stage];
        #pragma unroll
        for (int q = 0; q < 4; q++) acc[q] *= sc;
    } else {
        for (int v = 0; v < 15; v++){
            float win[18];
            #pragma unroll
            for (int j = 0; j < 18; j++) win[j] = su[(rbase+j)*46 + tx_+v];
            #pragma unroll
            for (int u = 0; u < 15; u++){
                float kv = sk[u*15+v];
                #pragma unroll
                for (int q = 0; q < 4; q++) acc[q] = fmaf(kv, win[u+q], acc[q]);
            }
        }
        __syncthreads();
    }

    // ---- regularizer term ----
    if (inter && p2){
        int nt4 = g_Snt4[stage];
        #pragma unroll
        for (int q = 0; q < 4; q++){
            const float* base = &sx[rbase+q+4][tx_+4];
            float a2 = acc[q];
            for (int t = 0; t < nt4; t += 4){
                a2 = fmaf(sSv[t],   base[sSo[t]],   a2);
                a2 = fmaf(sSv[t+1], base[sSo[t+1]], a2);
                a2 = fmaf(sSv[t+2], base[sSo[t+2]], a2);
                a2 = fmaf(sSv[t+3], base[sSo[t+3]], a2);
            }
            acc[q] = a2;
        }
        if (csrc){
            const float* cp = csrc + z*NPIX;
            #pragma unroll
            for (int q = 0; q < 4; q++)
                acc[q] -= cp[(Y0+rbase+q)*WV + X0 + tx_];
        }
    } else {
        for (int m = 0; m < 5; m++){
            float wm = rkw[stage*5+m];
            float pm = rpow[stage*5+m];
            float wp = wm*pm;
            int nt = g_rknt[stage][m];
            float* sph = pool + m*1296;
            const float* tg = tgt ? (tgt + (b*5+m)*CN + c*NPIX) : nullptr;
            float* vd = vdst + (b*5+m)*CN + c*NPIX;
            if (nt <= 4){
                T4 tf = t4_fwd_rk(stage, m, 40);
                for (int row = ty_; row < 36; row += 8){
                    int gy = Y0 - 2 + row;
                    bool iny = (unsigned)gy < HV;
                    bool rin = (row >= 2 && row < 34);
                    for (int col = tx_; col < 36; col += 32){
                        int gx = X0 - 2 + col;
                        float ph = 0.f;
                        if (iny && (unsigned)gx < WV){
                            float vv = c4(&sx[row][col], tf, 0.f);
                            int gi = gy*WV + gx;
                            if (tg) vv -= tg[gi];
                            if (p2){
                                ph = wp*sgnf(vv)*(fabsf(vv)+EPSF);
                            } else {
                                ph = wp*sgnf(vv)*powx(fabsf(vv)+EPSF, pm-1.f);
                                if (rin && col >= 2 && col < 34) vd[gi] = vv;
                            }
                        }
                        sph[row*36+col] = ph;
                    }
                }
            } else {
                for (int row = ty_; row < 36; row += 8){
                    int gy = Y0 - 2 + row;
                    bool iny = (unsigned)gy < HV;
                    bool rin = (row >= 2 && row < 34);
                    for (int col = tx_; col < 36; col += 32){
                        int gx = X0 - 2 + col;
                        float ph = 0.f;
                        if (iny && (unsigned)gx < WV){
                            float vv = cg_fwd_rk(&sx[row][col], stage, m, nt, 40, 0.f);
                            int gi = gy*WV + gx;
                            if (tg) vv -= tg[gi];
                            if (p2){
                                ph = wp*sgnf(vv)*(fabsf(vv)+EPSF);
                            } else {
                                ph = wp*sgnf(vv)*powx(fabsf(vv)+EPSF, pm-1.f);
                                if (rin && col >= 2 && col < 34) vd[gi] = vv;
                            }
                        }
                        sph[row*36+col] = ph;
                    }
                }
            }
        }
        __syncthreads();
        for (int m = 0; m < 5; m++){
            int nt = g_rknt[stage][m];
            const float* sph = pool + m*1296;
            if (nt <= 4){
                T4 ta = t4_adj_rk(stage, m, 36);
                #pragma unroll
                for (int q = 0; q < 4; q++)
                    acc[q] = c4(sph + (rbase+q)*36 + tx_, ta, acc[q]);
            } else {
                for (int q = 0; q < 4; q++)
                    acc[q] = cg_adj_rk(sph + (rbase+q)*36 + tx_, stage, m, nt, 36, acc[q]);
            }
        }
    }

    float* ro = rdst + z*NPIX;
    float ss = 0.f;
    #pragma unroll
    for (int q = 0; q < 4; q++){
        ro[(Y0+rbase+q)*WV + X0 + tx_] = -acc[q];
        ss = fmaf(acc[q], acc[q], ss);
    }
    __syncthreads();
    sh[tid] = ss; __syncthreads();
    for (int o = 128; o; o >>= 1){ if (tid < o) sh[tid] += sh[tid+o]; __syncthreads(); }
    if (tid == 0) g_partR[b*768 + c*256 + pslot] = sh[0];
}

// ---------------- prior targets + c-term ----------------
__global__ void __launch_bounds__(256)
k_prior(const float* __restrict__ xsrc, float* __restrict__ dst, float* __restrict__ cdst,
        const float* __restrict__ thr,
        const float* __restrict__ rkw, const float* __restrict__ rpow, int stage)
{
    int z = blockIdx.z; int b = z/CV, c = z - b*CV;
    __shared__ float sxx[1600];
    __shared__ float pool[6480];
    int tx_ = threadIdx.x, ty_ = threadIdx.y;
    int tid = ty_*32 + tx_;
    int X0 = blockIdx.x*32, Y0 = blockIdx.y*32;
    const float* xp = xsrc + z*NPIX;
    for (int row = ty_; row < 40; row += 8){
        int gy = Y0-4+row;
        bool iny = (unsigned)gy < HV;
        for (int col = tx_; col < 40; col += 32){
            int gx = X0-4+col;
            sxx[row*40+col] = (iny && (unsigned)gx < WV) ? xp[gy*WV+gx] : 0.f;
        }
    }
    __syncthreads();
    int rbase = ty_*4;
    int gxo = X0 + tx_;
    for (int m = 0; m < 5; m++){
        int nt = g_rknt[stage][m];
        float th = thr[m];
        float wp = rkw[stage*5+m]*rpow[stage*5+m];
        float* sph = pool + m*1296;
        T4 tf = t4_fwd_rk(stage, m, 40);
        for (int row = ty_; row < 36; row += 8){
            int gy = Y0-2+row;
            bool iny = (unsigned)gy < HV;
            bool rin = (row >= 2 && row < 34);
            for (int col = tx_; col < 36; col += 32){
                int gx = X0-2+col;
                float shr = 0.f;
                if (iny && (unsigned)gx < WV){
                    float v;
                    if (nt <= 4) v = c4(&sxx[row*40+col], tf, 0.f);
                    else v = cg_fwd_rk(&sxx[row*40+col], stage, m, nt, 40, 0.f);
                    shr = sgnf(v)*fmaxf(fabsf(v)-th, 0.f);
                    if (rin && col >= 2 && col < 34)
                        dst[(b*5+m)*CN + c*NPIX + gy*WV + gx] = shr;
                }
                sph[row*36+col] = wp*shr;
            }
        }
    }
    __syncthreads();
    float cacc[4] = {0,0,0,0};
    for (int m = 0; m < 5; m++){
        int nt = g_rknt[stage][m];
        const float* sph = pool + m*1296;
        if (nt <= 4){
            T4 ta = t4_adj_rk(stage, m, 36);
            #pragma unroll
            for (int q = 0; q < 4; q++)
                cacc[q] = c4(sph + (rbase+q)*36 + tx_, ta, cacc[q]);
        } else {
            for (int q = 0; q < 4; q++)
                cacc[q] = cg_adj_rk(sph + (rbase+q)*36 + tx_, stage, m, nt, 36, cacc[q]);
        }
    }
    #pragma unroll
    for (int q = 0; q < 4; q++)
        cdst[z*NPIX + (Y0+rbase+q)*WV + gxo] = cacc[q];
}

// ---------------- bilateral grid (coalesced splat, folded x+alpha*p) ----------------
__global__ void __launch_bounds__(256)
k_splat(const float* __restrict__ x, const float* __restrict__ p,
        float* __restrict__ grid, int slot){
    int pcgy = blockIdx.x;
    int gy = pcgy & 63;
    int pc = pcgy >> 6;
    int b = pc / CV;
    int tid = threadIdx.x;
    __shared__ float srow[4096];
    __shared__ float sh[256], sh2[256], s_alpha;
    float al = alpha_reduce(b, slot, tid, sh, sh2, &s_alpha);
    const float* xp = x + pc*NPIX + (gy*8)*WV;
    const float* pq = p + pc*NPIX + (gy*8)*WV;
    for (int i = tid; i < 4096; i += 256) srow[i] = fmaf(al, pq[i], xp[i]);
    __syncthreads();
    if (tid < 64){
        int gx = tid;
        float bv[NBIN], bw[NBIN];
        #pragma unroll
        for (int z = 0; z < NBIN; z++){ bv[z] = 0.f; bw[z] = 0.f; }
        for (int dy = 0; dy < 8; dy++)
            for (int dx = 0; dx < 8; dx++){
                float I = srow[dy*512 + gx*8+dx];
                float Ic = fminf(fmaxf(I, 0.f), 1.f);
                int zi = (int)rintf(Ic * (float)(NBIN-1));
                zi = max(0, min(NBIN-1, zi));
                bv[zi] += Ic; bw[zi] += 1.f;
            }
        float* gp = grid + ((long)pcgy*64 + gx)*NBIN*2;
        #pragma unroll
        for (int z = 0; z < NBIN; z++){ gp[z*2] = bv[z]; gp[z*2+1] = bw[z]; }
    }
}

// fused separable grid filter: y-conv (11) -> x-conv (11) -> z-conv (5), one launch.
__global__ void __launch_bounds__(256)
k_bconv(const float* __restrict__ gin, float* __restrict__ gout,
        const float* __restrict__ fs, const float* __restrict__ fr)
{
    int blk = blockIdx.x;
    int txt = blk & 7; int tyt = (blk >> 3) & 7; int pc = blk >> 6;
    int Y0 = tyt*8, X0 = txt*8;
    __shared__ float sin[18*18*18];
    __shared__ float sy [8*18*18];
    __shared__ float sxz[8*8*18];
    __shared__ float sfs[11], sfr[5];
    int tid = threadIdx.x;
    const float* gp = gin + (long)pc*(GH*GW*NBIN*2);
    for (int i = tid; i < 18*18*18; i += 256){
        int k = i % 18; int rc = i / 18;
        int c0 = rc % 18, r0 = rc / 18;
        int gy = Y0 - 5 + r0, gx = X0 - 5 + c0;
        float v = 0.f;
        if ((unsigned)gy < GH && (unsigned)gx < GW)
            v = gp[(gy*GW + gx)*18 + k];
        sin[i] = v;
    }
    if (tid < 11) sfs[tid] = fs[tid];
    if (tid < 5)  sfr[tid] = fr[tid];
    __syncthreads();
    for (int i = tid; i < 8*18*18; i += 256){
        int k = i % 18; int rc = i / 18;
        int c0 = rc % 18, r0 = rc / 18;
        const float* bp = sin + (r0*18 + c0)*18 + k;
        float s = 0.f;
        #pragma unroll
        for (int t = 0; t < 11; t++) s = fmaf(sfs[t], bp[t*324], s);
        sy[i] = s;
    }
    __syncthreads();
    for (int i = tid; i < 8*8*18; i += 256){
        int k = i % 18; int rc = i / 18;
        int c0 = rc % 8, r0 = rc / 8;
        const float* bp = sy + (r0*18 + c0)*18 + k;
        float s = 0.f;
        #pragma unroll
        for (int t = 0; t < 11; t++) s = fmaf(sfs[t], bp[t*18], s);
        sxz[i] = s;
    }
    __syncthreads();
    float* go = gout + (long)pc*(GH*GW*NBIN*2);
    for (int i = tid; i < 8*8*18; i += 256){
        int k = i % 18; int rc = i / 18;
        int ch = k & 1; int zz = k >> 1;
        const float* bp = sxz + rc*18 + ch;
        float s = 0.f;
        #pragma unroll
        for (int t = 0; t < 5; t++){
            int cc = zz + t - 2;
            if ((unsigned)cc < NBIN) s = fmaf(sfr[t], bp[cc*2], s);
        }
        int r0 = rc / 8, c0 = rc % 8;
        go[((Y0+r0)*GW + X0+c0)*18 + k] = s;
    }
}

// slice with folded x+alpha*p input; writes result to xout
__global__ void k_slice(const float* __restrict__ xsrc, const float* __restrict__ psrc,
                        float* __restrict__ xout, const float* __restrict__ grid, int slot){
    int i = blockIdx.x*blockDim.x + threadIdx.x;
    int tid = threadIdx.x;
    int pc = i / NPIX;
    int b = pc / CV;
    __shared__ float sh[256], sh2[256], s_alpha;
    float al = alpha_reduce(b, slot, tid, sh, sh2, &s_alpha);
    if (i >= BCN) return;
    int pix = i - pc*NPIX;
    int y = pix / WV, xx = pix - y*WV;
    float I = fmaf(al, psrc[i], xsrc[i]);
    float Ic = fminf(fmaxf(I, 0.f), 1.f);
    float yf = (float)y * 0.125f;
    float xf = (float)xx * 0.125f;
    float zf = Ic * (float)(NBIN-1);
    int y0 = max(0, min(GH-1, (int)floorf(yf)));  int y1 = min(y0+1, GH-1);
    float wy = fminf(fmaxf(yf - (float)y0, 0.f), 1.f);
    int x0 = max(0, min(GW-1, (int)floorf(xf)));  int x1 = min(x0+1, GW-1);
    float wx = fminf(fmaxf(xf - (float)x0, 0.f), 1.f);
    int z0 = max(0, min(NBIN-1, (int)floorf(zf))); int z1 = min(z0+1, NBIN-1);
    float wz = fminf(fmaxf(zf - (float)z0, 0.f), 1.f);
    const float* gp = grid + (long)pc*GH*GW*NBIN*2;
    float a0 = 0.f, a1 = 0.f;
    int ys[2]   = {y0, y1};  float wys[2] = {1.f-wy, wy};
    int xs[2]   = {x0, x1};  float wxs[2] = {1.f-wx, wx};
    int zs[2]   = {z0, z1};  float wzs[2] = {1.f-wz, wz};
    for (int a = 0; a < 2; a++)
        for (int bb = 0; bb < 2; bb++)
            for (int cc = 0; cc < 2; cc++){
                float w = wys[a]*wxs[bb]*wzs[cc];
                int idx = (((ys[a]*GW) + xs[bb])*NBIN + zs[cc])*2;
                a0 = fmaf(w, gp[idx], a0);
                a1 = fmaf(w, gp[idx+1], a1);
            }
    xout[i] = a0 / (a1 + 1e-8f);
}

// ---------------- host orchestration ----------------
extern "C" void kernel_launch(void* const* d_in, const int* in_sizes, int n_in,
                              void* d_out, int out_size)
{
    const float* blurred = (const float*)d_in[0];
    const float* kern    = (const float*)d_in[1];
    const float* dks     = (const float*)d_in[2];
    const float* dkw     = (const float*)d_in[3];
    const float* rks     = (const float*)d_in[4];
    const float* rkw     = (const float*)d_in[5];
    const float* rpow    = (const float*)d_in[6];
    const float* fs      = (const float*)d_in[7];
    const float* fr      = (const float*)d_in[8];
    const float* thr     = (const float*)d_in[9];
    const int NCG = 5;

    float *px, *px2, *pr, *pp, *pp2, *pt, *pt2, *ptp, *pv, *ptg, *pgA, *pgB;
    cudaGetSymbolAddress((void**)&px,  g_x);
    cudaGetSymbolAddress((void**)&px2, g_x2);
    cudaGetSymbolAddress((void**)&pr,  g_r);
    cudaGetSymbolAddress((void**)&pp,  g_p);
    cudaGetSymbolAddress((void**)&pp2, g_p2);
    cudaGetSymbolAddress((void**)&pt,  g_t);
    cudaGetSymbolAddress((void**)&pt2, g_t2);
    cudaGetSymbolAddress((void**)&ptp, g_tp);
    cudaGetSymbolAddress((void**)&pv,  g_v);
    cudaGetSymbolAddress((void**)&ptg, g_tgt);
    cudaGetSymbolAddress((void**)&pgA, g_gridA);
    cudaGetSymbolAddress((void**)&pgB, g_gridB);

    dim3 cb(32, 8);
    dim3 cg15(16, 4, BV*CV);   // 32x128 tiles, RY=16
    dim3 cg32(16, 16, BV*CV);  // 32x32 tiles (gradfull/prior)
    int EW = (BCN + 255)/256;

    k_prep<<<1,32>>>(dks, dkw, rks, rkw, rpow);

    const float* s0x = nullptr; const float* s0p = nullptr; int s0slot = 0;
    auto cgrun = [&](int stage, const float* tgt, const float* cbuf,
                     const float* xin, float* xfinal){
        float* tcur = pt;   float* tnxt = pt2;
        float* pcur = pp;   float* pnxt = pp2;
        k_conv15<<<cg15,cb>>>(xin, tcur, kern, blurred);
        float* xcur = (xin == px) ? px2 : px;
        k_gradfull<<<cg32,cb>>>(xin, pcur, tcur, ptp, xcur, tnxt, tgt, cbuf, pr, pv,
                                kern, rkw, rpow, stage, 0, 1);
        { float* q = tcur; tcur = tnxt; tnxt = q; }
        for (int it = 0; it < NCG; it++){
            int rs = it & 1, ws = rs ^ 1;
            k_pstep<<<cg15,cb>>>(pcur, pnxt, ptp, pr, kern, rkw, rpow, stage, it == 0, rs);
            if (it == NCG-1){
                if (xfinal){
                    k_axpy_final<<<dim3(256,BV),256>>>(xcur, pnxt, xfinal, ws);
                } else {
                    s0x = xcur; s0p = pnxt; s0slot = ws;
                }
            } else {
                float* xd = (xcur == px) ? px2 : px;
                k_gradfull<<<cg32,cb>>>(xcur, pnxt, tcur, ptp, xd, tnxt, tgt, cbuf, pr, pv,
                                        kern, rkw, rpow, stage, ws, 0);
                xcur = xd;
                { float* q = tcur; tcur = tnxt; tnxt = q; }
            }
            { float* q = pcur; pcur = pnxt; pnxt = q; }
        }
    };

    // Stage 0 (targets = 0, c = 0); final axpy deferred into splat/slice
    cgrun(0, nullptr, nullptr, blurred, nullptr);

    float* xbi = (s0x == px) ? px2 : px;
    k_splat<<<BV*CV*GH, 256>>>(s0x, s0p, pgA, s0slot);
    k_bconv<<<BV*CV*64, 256>>>(pgA, pgB, fs, fr);
    k_slice<<<EW,256>>>(s0x, s0p, xbi, pgB, s0slot);

    k_prior<<<cg32,cb>>>(xbi, ptg, pv, thr, rkw, rpow, 1);
    cgrun(1, ptg, pv, xbi, (float*)d_out);
}